// round 1
// baseline (speedup 1.0000x reference)
#include <cuda_runtime.h>
#include <math.h>

// Problem constants
#define BB 256
#define LL 256
#define DD 512
#define HH 8
#define DHH 64
#define NLAYER 6
#define FFD 2048
#define TT (BB*LL)          // 65536 tokens
#define NATOM 32768

// ---------------- scratch (device globals; no allocation allowed) -----------
__device__ float g_h  [(size_t)TT*DD];
__device__ float g_hn [(size_t)TT*DD];
__device__ float g_q  [(size_t)TT*DD];
__device__ float g_k  [(size_t)TT*DD];
__device__ float g_v  [(size_t)TT*DD];
__device__ float g_ctx[(size_t)TT*DD];
__device__ float g_att[(size_t)BB*HH*LL*LL];   // 536 MB
__device__ float g_ff [(size_t)TT*FFD];        // 536 MB

// ---------------- helpers ---------------------------------------------------
template<bool DOMAX>
__device__ __forceinline__ float block_reduce(float v, float* red) {
    __syncthreads();
    #pragma unroll
    for (int o = 16; o; o >>= 1) {
        float other = __shfl_xor_sync(0xffffffffu, v, o);
        v = DOMAX ? fmaxf(v, other) : (v + other);
    }
    if ((threadIdx.x & 31) == 0) red[threadIdx.x >> 5] = v;
    __syncthreads();
    if (threadIdx.x == 0) {
        float t = red[0];
        #pragma unroll
        for (int i = 1; i < 8; i++) t = DOMAX ? fmaxf(t, red[i]) : (t + red[i]);
        red[0] = t;
    }
    __syncthreads();
    return red[0];
}

// ---------------- embedding -------------------------------------------------
// h[b*L+l, :] = rate1 * emb_table[x[l,b]]
__global__ void embed_kernel(const int* __restrict__ x, const float* __restrict__ emb,
                             const float* __restrict__ rate1, float* __restrict__ h) {
    int idx = blockIdx.x * blockDim.x + threadIdx.x;   // over TT*DD/4
    int t = idx / (DD/4);
    int c = idx % (DD/4);
    int b = t / LL, l = t % LL;
    int tok = x[l*BB + b];
    float4 e = ((const float4*)(emb + (size_t)tok*DD))[c];
    float r = rate1[0];
    float4 o = make_float4(r*e.x, r*e.y, r*e.z, r*e.w);
    ((float4*)(h + (size_t)t*DD))[c] = o;
}

// h[batch_index[a], atoms_index[a]+1, :] += rate2 * (emb[tok] + coord@cw + cb)
__global__ void atom_kernel(const float* __restrict__ coord, const int* __restrict__ atok,
                            const int* __restrict__ aidx, const int* __restrict__ bidx,
                            const float* __restrict__ emb, const float* __restrict__ cw,
                            const float* __restrict__ cb, const float* __restrict__ rate2,
                            float* __restrict__ h) {
    int a = blockIdx.x;
    int tok = atok[a];
    float c0 = coord[a*3+0], c1 = coord[a*3+1], c2 = coord[a*3+2];
    size_t row = (size_t)(bidx[a]*LL + aidx[a] + 1) * DD;
    float r = rate2[0];
    for (int i = threadIdx.x; i < DD; i += blockDim.x) {
        float val = emb[(size_t)tok*DD + i] + c0*cw[i] + c1*cw[DD+i] + c2*cw[2*DD+i] + cb[i];
        h[row + i] += r * val;
    }
}

// ---------------- layernorm -------------------------------------------------
__global__ void ln_kernel(const float* __restrict__ in, float* __restrict__ out,
                          const float* __restrict__ g, const float* __restrict__ bt) {
    __shared__ float red[8];
    size_t t = blockIdx.x;
    const float* row = in + t*DD;
    int tid = threadIdx.x;
    float v0 = row[tid], v1 = row[tid+256];
    float mean = block_reduce<false>(v0+v1, red) * (1.0f/DD);
    float d0 = v0-mean, d1 = v1-mean;
    float var = block_reduce<false>(d0*d0+d1*d1, red) * (1.0f/DD);
    float rs = rsqrtf(var + 1e-6f);
    out[t*DD+tid]     = d0*rs*g[tid]     + bt[tid];
    out[t*DD+tid+256] = d1*rs*g[tid+256] + bt[tid+256];
}

// final LN + transpose [B,L,D] -> [L,B,D]
__global__ void lnf_kernel(const float* __restrict__ in, float* __restrict__ out,
                           const float* __restrict__ g, const float* __restrict__ bt) {
    __shared__ float red[8];
    size_t t = blockIdx.x;
    int b = (int)(t / LL), l = (int)(t % LL);
    const float* row = in + t*DD;
    int tid = threadIdx.x;
    float v0 = row[tid], v1 = row[tid+256];
    float mean = block_reduce<false>(v0+v1, red) * (1.0f/DD);
    float d0 = v0-mean, d1 = v1-mean;
    float var = block_reduce<false>(d0*d0+d1*d1, red) * (1.0f/DD);
    float rs = rsqrtf(var + 1e-6f);
    size_t o = (size_t)(l*BB + b) * DD;
    out[o+tid]     = d0*rs*g[tid]     + bt[tid];
    out[o+tid+256] = d1*rs*g[tid+256] + bt[tid+256];
}

// ---------------- generic SGEMM: C = A[M,K] @ B[K,N] + bias (+Res)(+ReLU) ---
// BM=BN=128, BK=8, 256 threads, 8x8 per thread. M%128==0, N%128==0, K%8==0.
template<int RELU, int RESID>
__global__ __launch_bounds__(256)
void gemm_kernel(int M, int N, int K,
                 const float* __restrict__ A, const float* __restrict__ Bm,
                 const float* __restrict__ bias, const float* __restrict__ Res,
                 float* __restrict__ C) {
    __shared__ float As[8][128];
    __shared__ float Bs[8][128];
    int bm = blockIdx.y, bn = blockIdx.x;
    int tid = threadIdx.x;
    int arow = tid >> 1;           // 0..127
    int acol = (tid & 1) * 4;      // 0 or 4
    int brow = tid >> 5;           // 0..7
    int bcol = (tid & 31) * 4;     // 0..124
    const float* Aptr = A + (size_t)(bm*128 + arow)*K + acol;
    const float* Bptr = Bm + (size_t)brow*N + bn*128 + bcol;
    int tr = (tid >> 4) * 8;
    int tc = (tid & 15) * 8;
    float acc[8][8] = {};
    for (int k0 = 0; k0 < K; k0 += 8) {
        float4 a4 = *(const float4*)Aptr;  Aptr += 8;
        As[acol+0][arow] = a4.x; As[acol+1][arow] = a4.y;
        As[acol+2][arow] = a4.z; As[acol+3][arow] = a4.w;
        *(float4*)&Bs[brow][bcol] = *(const float4*)Bptr;  Bptr += (size_t)8*N;
        __syncthreads();
        #pragma unroll
        for (int kk = 0; kk < 8; kk++) {
            float4 a0 = *(const float4*)&As[kk][tr];
            float4 a1 = *(const float4*)&As[kk][tr+4];
            float4 b0 = *(const float4*)&Bs[kk][tc];
            float4 b1 = *(const float4*)&Bs[kk][tc+4];
            float ra[8] = {a0.x,a0.y,a0.z,a0.w,a1.x,a1.y,a1.z,a1.w};
            float rb[8] = {b0.x,b0.y,b0.z,b0.w,b1.x,b1.y,b1.z,b1.w};
            #pragma unroll
            for (int i = 0; i < 8; i++)
                #pragma unroll
                for (int j = 0; j < 8; j++)
                    acc[i][j] += ra[i]*rb[j];
        }
        __syncthreads();
    }
    #pragma unroll
    for (int i = 0; i < 8; i++) {
        size_t m = (size_t)bm*128 + tr + i;
        #pragma unroll
        for (int j = 0; j < 8; j += 4) {
            int n = bn*128 + tc + j;
            float4 r = make_float4(acc[i][j], acc[i][j+1], acc[i][j+2], acc[i][j+3]);
            float4 bs = *(const float4*)(bias + n);
            r.x += bs.x; r.y += bs.y; r.z += bs.z; r.w += bs.w;
            if (RESID) {
                float4 rr = *(const float4*)(Res + m*N + n);
                r.x += rr.x; r.y += rr.y; r.z += rr.z; r.w += rr.w;
            }
            if (RELU) {
                r.x = fmaxf(r.x, 0.f); r.y = fmaxf(r.y, 0.f);
                r.z = fmaxf(r.z, 0.f); r.w = fmaxf(r.w, 0.f);
            }
            *(float4*)(C + m*N + n) = r;
        }
    }
}

// ---------------- attention scores: att[b,h,i,j] = scale*q·k, masked --------
// grid (L/64, L/64, B*H), 256 threads, 64x64 tile, K=64.
__global__ __launch_bounds__(256)
void scores_kernel(const float* __restrict__ q, const float* __restrict__ kmat,
                   const int* __restrict__ x, float* __restrict__ att) {
    int bh = blockIdx.z, b = bh >> 3, h = bh & 7;
    int i0 = blockIdx.y*64, j0 = blockIdx.x*64;
    __shared__ float Qs[64][68];   // [d][i]
    __shared__ float Ks[64][68];   // [d][j]
    __shared__ int padf[64];
    int tid = threadIdx.x;
    #pragma unroll
    for (int it = 0; it < 4; it++) {
        int lin = tid + it*256;
        int r = lin >> 4;
        int c4 = (lin & 15) * 4;
        float4 qv = *(const float4*)(q    + (size_t)(b*LL + i0 + r)*DD + h*DHH + c4);
        Qs[c4+0][r]=qv.x; Qs[c4+1][r]=qv.y; Qs[c4+2][r]=qv.z; Qs[c4+3][r]=qv.w;
        float4 kv = *(const float4*)(kmat + (size_t)(b*LL + j0 + r)*DD + h*DHH + c4);
        Ks[c4+0][r]=kv.x; Ks[c4+1][r]=kv.y; Ks[c4+2][r]=kv.z; Ks[c4+3][r]=kv.w;
    }
    if (tid < 64) padf[tid] = (x[(j0+tid)*BB + b] == 0);
    __syncthreads();
    int ty = tid >> 4, tx = tid & 15;
    float acc[4][4] = {};
    #pragma unroll
    for (int d = 0; d < 64; d++) {
        float4 a = *(const float4*)&Qs[d][ty*4];
        float4 bb = *(const float4*)&Ks[d][tx*4];
        float ra[4] = {a.x,a.y,a.z,a.w};
        float rb[4] = {bb.x,bb.y,bb.z,bb.w};
        #pragma unroll
        for (int i = 0; i < 4; i++)
            #pragma unroll
            for (int j = 0; j < 4; j++)
                acc[i][j] += ra[i]*rb[j];
    }
    const float scale = 0.125f;   // 1/sqrt(64)
    #pragma unroll
    for (int ii = 0; ii < 4; ii++) {
        int i = i0 + ty*4 + ii;
        #pragma unroll
        for (int jj = 0; jj < 4; jj++) {
            int j = j0 + tx*4 + jj;
            float val = padf[tx*4+jj] ? -1e9f : acc[ii][jj]*scale;
            att[((size_t)bh*LL + i)*LL + j] = val;
        }
    }
}

// ---------------- softmax over last dim (rows of 256) -----------------------
__global__ void softmax_kernel(float* __restrict__ att) {
    __shared__ float red[8];
    float* p = att + (size_t)blockIdx.x * LL;
    float v = p[threadIdx.x];
    float m = block_reduce<true>(v, red);
    float e = __expf(v - m);
    float s = block_reduce<false>(e, red);
    p[threadIdx.x] = e / s;
}

// ---------------- ctx = att @ v : per (b,h) [256x256]@[256x64] --------------
// grid (L/64, B*H), 256 threads, 64x64 output tile (i x dh), K chunks of 16.
__global__ __launch_bounds__(256)
void ctx_kernel(const float* __restrict__ att, const float* __restrict__ v,
                float* __restrict__ ctx) {
    int bh = blockIdx.y, b = bh >> 3, h = bh & 7;
    int i0 = blockIdx.x*64;
    __shared__ float Ats[16][68];   // [k][i]
    __shared__ float Vs[16][64];    // [k][dh]
    int tid = threadIdx.x;
    int ty = tid >> 4, tx = tid & 15;
    float acc[4][4] = {};
    for (int k0 = 0; k0 < LL; k0 += 16) {
        {   int r = tid >> 2, c4 = (tid & 3) * 4;
            float4 a = *(const float4*)(att + ((size_t)bh*LL + i0 + r)*LL + k0 + c4);
            Ats[c4+0][r]=a.x; Ats[c4+1][r]=a.y; Ats[c4+2][r]=a.z; Ats[c4+3][r]=a.w; }
        {   int r = tid >> 4, c4 = (tid & 15) * 4;
            *(float4*)&Vs[r][c4] = *(const float4*)(v + (size_t)(b*LL + k0 + r)*DD + h*DHH + c4); }
        __syncthreads();
        #pragma unroll
        for (int kk = 0; kk < 16; kk++) {
            float4 a = *(const float4*)&Ats[kk][ty*4];
            float4 bb = *(const float4*)&Vs[kk][tx*4];
            float ra[4] = {a.x,a.y,a.z,a.w};
            float rb[4] = {bb.x,bb.y,bb.z,bb.w};
            #pragma unroll
            for (int i = 0; i < 4; i++)
                #pragma unroll
                for (int j = 0; j < 4; j++)
                    acc[i][j] += ra[i]*rb[j];
        }
        __syncthreads();
    }
    #pragma unroll
    for (int ii = 0; ii < 4; ii++)
        #pragma unroll
        for (int jj = 0; jj < 4; jj++)
            ctx[(size_t)(b*LL + i0 + ty*4 + ii)*DD + h*DHH + tx*4 + jj] = acc[ii][jj];
}

// ---------------- host driver ------------------------------------------------
extern "C" void kernel_launch(void* const* d_in, const int* in_sizes, int n_in,
                              void* d_out, int out_size) {
    const int*   x           = (const int*)  d_in[0];
    const float* atoms_coord = (const float*)d_in[1];
    const int*   atoms_token = (const int*)  d_in[2];
    const int*   atoms_index = (const int*)  d_in[3];
    const int*   batch_index = (const int*)  d_in[4];
    const float* emb         = (const float*)d_in[5];
    const float* coord_w     = (const float*)d_in[6];
    const float* coord_b     = (const float*)d_in[7];
    const float* rate1       = (const float*)d_in[8];
    const float* rate2       = (const float*)d_in[9];
    const float* ln1_g       = (const float*)d_in[10];
    const float* ln1_b       = (const float*)d_in[11];
    const float* wq          = (const float*)d_in[12];
    const float* bq          = (const float*)d_in[13];
    const float* wk          = (const float*)d_in[14];
    const float* bk          = (const float*)d_in[15];
    const float* wv          = (const float*)d_in[16];
    const float* bv          = (const float*)d_in[17];
    const float* wo          = (const float*)d_in[18];
    const float* bo          = (const float*)d_in[19];
    const float* ln2_g       = (const float*)d_in[20];
    const float* ln2_b       = (const float*)d_in[21];
    const float* w1          = (const float*)d_in[22];
    const float* b1          = (const float*)d_in[23];
    const float* w2          = (const float*)d_in[24];
    const float* b2          = (const float*)d_in[25];
    const float* lnf_g       = (const float*)d_in[26];
    const float* lnf_b       = (const float*)d_in[27];
    float* out = (float*)d_out;

    float *h, *hn, *q, *k, *v, *ctx, *att, *ff;
    cudaGetSymbolAddress((void**)&h,   g_h);
    cudaGetSymbolAddress((void**)&hn,  g_hn);
    cudaGetSymbolAddress((void**)&q,   g_q);
    cudaGetSymbolAddress((void**)&k,   g_k);
    cudaGetSymbolAddress((void**)&v,   g_v);
    cudaGetSymbolAddress((void**)&ctx, g_ctx);
    cudaGetSymbolAddress((void**)&att, g_att);
    cudaGetSymbolAddress((void**)&ff,  g_ff);

    // embedding + atom scatter
    embed_kernel<<<(TT*(DD/4))/256, 256>>>(x, emb, rate1, h);
    atom_kernel<<<NATOM, 128>>>(atoms_coord, atoms_token, atoms_index, batch_index,
                                emb, coord_w, coord_b, rate2, h);

    dim3 gD(DD/128, TT/128);       // N=512 GEMMs
    dim3 gF(FFD/128, TT/128);      // N=2048 GEMM
    dim3 gS(LL/64, LL/64, BB*HH);  // scores
    dim3 gC(LL/64, BB*HH);         // ctx

    for (int l = 0; l < NLAYER; l++) {
        const float* lwq = wq + (size_t)l*DD*DD;
        const float* lwk = wk + (size_t)l*DD*DD;
        const float* lwv = wv + (size_t)l*DD*DD;
        const float* lwo = wo + (size_t)l*DD*DD;
        const float* lw1 = w1 + (size_t)l*DD*FFD;
        const float* lw2 = w2 + (size_t)l*FFD*DD;

        ln_kernel<<<TT, 256>>>(h, hn, ln1_g + l*DD, ln1_b + l*DD);
        gemm_kernel<0,0><<<gD, 256>>>(TT, DD, DD, hn, lwq, bq + l*DD, nullptr, q);
        gemm_kernel<0,0><<<gD, 256>>>(TT, DD, DD, hn, lwk, bk + l*DD, nullptr, k);
        gemm_kernel<0,0><<<gD, 256>>>(TT, DD, DD, hn, lwv, bv + l*DD, nullptr, v);
        scores_kernel<<<gS, 256>>>(q, k, x, att);
        softmax_kernel<<<(size_t)BB*HH*LL, 256>>>(att);
        ctx_kernel<<<gC, 256>>>(att, v, ctx);
        gemm_kernel<0,1><<<gD, 256>>>(TT, DD, DD, ctx, lwo, bo + l*DD, h, h);
        ln_kernel<<<TT, 256>>>(h, hn, ln2_g + l*DD, ln2_b + l*DD);
        gemm_kernel<1,0><<<gF, 256>>>(TT, FFD, DD, hn, lw1, b1 + l*FFD, nullptr, ff);
        gemm_kernel<0,1><<<gD, 256>>>(TT, DD, FFD, ff, lw2, b2 + l*DD, h, h);
    }
    lnf_kernel<<<TT, 256>>>(h, out, lnf_g, lnf_b);
}

// round 3
// speedup vs baseline: 2.5553x; 2.5553x over previous
#include <cuda_runtime.h>
#include <math.h>
#include <stdint.h>

// Problem constants
#define BB 256
#define LL 256
#define DD 512
#define HH 8
#define DHH 64
#define NLAYER 6
#define FFD 2048
#define TT (BB*LL)          // 65536 tokens
#define NATOM 32768

// ---------------- scratch (device globals; no allocation allowed) -----------
__device__ float g_h  [(size_t)TT*DD];
__device__ float g_hn [(size_t)TT*DD];
__device__ float g_q  [(size_t)TT*DD];
__device__ float g_k  [(size_t)TT*DD];
__device__ float g_v  [(size_t)TT*DD];
__device__ float g_ctx[(size_t)TT*DD];
__device__ float g_att[(size_t)BB*HH*LL*LL];   // 536 MB
__device__ float g_ff [(size_t)TT*FFD];        // 536 MB
#define WT_LSTRIDE 3145728
__device__ float g_wt [(size_t)NLAYER*WT_LSTRIDE];   // 75.5 MB

// ---------------- small helpers ----------------------------------------------
__device__ __forceinline__ uint32_t smem_u32(const void* p) {
    uint32_t a;
    asm("{ .reg .u64 t; cvta.to.shared.u64 t, %1; cvt.u32.u64 %0, t; }" : "=r"(a) : "l"(p));
    return a;
}
__device__ __forceinline__ float tf32r(float x) {
    uint32_t u; asm("cvt.rn.tf32.f32 %0, %1;" : "=r"(u) : "f"(x));
    return __uint_as_float(u);
}
__device__ __forceinline__ void cp_async16(uint32_t dst, const void* src) {
    asm volatile("cp.async.ca.shared.global [%0], [%1], 16;" :: "r"(dst), "l"(src) : "memory");
}
__device__ __forceinline__ void cp_commit() {
    asm volatile("cp.async.commit_group;" ::: "memory");
}
template<int N>
__device__ __forceinline__ void cp_wait() {
    asm volatile("cp.async.wait_group %0;" :: "n"(N) : "memory");
}
__device__ __forceinline__ void mma_tf32(float& d0, float& d1, float& d2, float& d3,
                                         uint32_t a0, uint32_t a1, uint32_t a2, uint32_t a3,
                                         uint32_t b0, uint32_t b1) {
    asm volatile(
        "mma.sync.aligned.m16n8k8.row.col.f32.tf32.tf32.f32 "
        "{%0,%1,%2,%3}, {%4,%5,%6,%7}, {%8,%9}, {%0,%1,%2,%3};"
        : "+f"(d0), "+f"(d1), "+f"(d2), "+f"(d3)
        : "r"(a0), "r"(a1), "r"(a2), "r"(a3), "r"(b0), "r"(b1));
}

// ---------------- block reduce ----------------------------------------------
template<bool DOMAX>
__device__ __forceinline__ float block_reduce(float v, float* red) {
    __syncthreads();
    #pragma unroll
    for (int o = 16; o; o >>= 1) {
        float other = __shfl_xor_sync(0xffffffffu, v, o);
        v = DOMAX ? fmaxf(v, other) : (v + other);
    }
    if ((threadIdx.x & 31) == 0) red[threadIdx.x >> 5] = v;
    __syncthreads();
    if (threadIdx.x == 0) {
        float t = red[0];
        #pragma unroll
        for (int i = 1; i < 8; i++) t = DOMAX ? fmaxf(t, red[i]) : (t + red[i]);
        red[0] = t;
    }
    __syncthreads();
    return red[0];
}

// ---------------- embedding -------------------------------------------------
__global__ void embed_kernel(const int* __restrict__ x, const float* __restrict__ emb,
                             const float* __restrict__ rate1, float* __restrict__ h) {
    int idx = blockIdx.x * blockDim.x + threadIdx.x;
    int t = idx / (DD/4);
    int c = idx % (DD/4);
    int b = t / LL, l = t % LL;
    int tok = x[l*BB + b];
    float4 e = ((const float4*)(emb + (size_t)tok*DD))[c];
    float r = rate1[0];
    ((float4*)(h + (size_t)t*DD))[c] = make_float4(r*e.x, r*e.y, r*e.z, r*e.w);
}

__global__ void atom_kernel(const float* __restrict__ coord, const int* __restrict__ atok,
                            const int* __restrict__ aidx, const int* __restrict__ bidx,
                            const float* __restrict__ emb, const float* __restrict__ cw,
                            const float* __restrict__ cb, const float* __restrict__ rate2,
                            float* __restrict__ h) {
    int a = blockIdx.x;
    int tok = atok[a];
    float c0 = coord[a*3+0], c1 = coord[a*3+1], c2 = coord[a*3+2];
    size_t row = (size_t)(bidx[a]*LL + aidx[a] + 1) * DD;
    float r = rate2[0];
    for (int i = threadIdx.x; i < DD; i += blockDim.x) {
        float val = emb[(size_t)tok*DD + i] + c0*cw[i] + c1*cw[DD+i] + c2*cw[2*DD+i] + cb[i];
        h[row + i] += r * val;
    }
}

// ---------------- layernorm (output tf32-rounded: feeds tensor GEMMs) -------
__global__ void ln_kernel(const float* __restrict__ in, float* __restrict__ out,
                          const float* __restrict__ g, const float* __restrict__ bt) {
    __shared__ float red[8];
    size_t t = blockIdx.x;
    const float* row = in + t*DD;
    int tid = threadIdx.x;
    float v0 = row[tid], v1 = row[tid+256];
    float mean = block_reduce<false>(v0+v1, red) * (1.0f/DD);
    float d0 = v0-mean, d1 = v1-mean;
    float var = block_reduce<false>(d0*d0+d1*d1, red) * (1.0f/DD);
    float rs = rsqrtf(var + 1e-6f);
    out[t*DD+tid]     = tf32r(d0*rs*g[tid]     + bt[tid]);
    out[t*DD+tid+256] = tf32r(d1*rs*g[tid+256] + bt[tid+256]);
}

// final LN + transpose [B,L,D] -> [L,B,D]
__global__ void lnf_kernel(const float* __restrict__ in, float* __restrict__ out,
                           const float* __restrict__ g, const float* __restrict__ bt) {
    __shared__ float red[8];
    size_t t = blockIdx.x;
    int b = (int)(t / LL), l = (int)(t % LL);
    const float* row = in + t*DD;
    int tid = threadIdx.x;
    float v0 = row[tid], v1 = row[tid+256];
    float mean = block_reduce<false>(v0+v1, red) * (1.0f/DD);
    float d0 = v0-mean, d1 = v1-mean;
    float var = block_reduce<false>(d0*d0+d1*d1, red) * (1.0f/DD);
    float rs = rsqrtf(var + 1e-6f);
    size_t o = (size_t)(l*BB + b) * DD;
    out[o+tid]     = d0*rs*g[tid]     + bt[tid];
    out[o+tid+256] = d1*rs*g[tid+256] + bt[tid+256];
}

// ---------------- weight transpose + tf32 round: Wt[n,k] = tf32(W[k,n]) -----
__global__ void transpose_tf32(const float* __restrict__ W, float* __restrict__ Wt,
                               int K, int N) {
    __shared__ float t[32][33];
    int k0 = blockIdx.x*32, n0 = blockIdx.y*32;
    int tx = threadIdx.x, ty = threadIdx.y;
    for (int i = ty; i < 32; i += 8)
        t[i][tx] = W[(size_t)(k0+i)*N + n0 + tx];
    __syncthreads();
    for (int i = ty; i < 32; i += 8)
        Wt[(size_t)(n0+i)*K + k0 + tx] = tf32r(t[tx][i]);
}

// ---------------- mma.sync tf32 GEMM: C[M,N] = A[M,K] @ Wt[N,K]^T -----------
// BM=BN=128, BK=32, 256 threads = 8 warps (4 along M x 2 along N), warp tile
// 32x64. Fragments via padded-stride SMEM (36 floats/row, conflict-free).
// Double-buffered cp.async pipeline. Epilogue: +bias, (+Res), (+ReLU->tf32).
#define SROW 36
#define TILE_F (128*SROW)          // floats per tile buffer
#define SMEM_GEMM (4*TILE_F*4)     // A0,A1,B0,B1 : 73728 bytes

template<int RELU, int RESID>
__global__ void __launch_bounds__(256)
mma_gemm(int K, const float* __restrict__ A, const float* __restrict__ Bt,
         const float* __restrict__ bias, const float* __restrict__ Res,
         float* __restrict__ C, int N) {
    extern __shared__ __align__(16) float dyn[];
    float* sA = dyn;               // [2][128][36]
    float* sB = dyn + 2*TILE_F;    // [2][128][36]
    uint32_t sA_u = smem_u32(sA);
    uint32_t sB_u = smem_u32(sB);

    int tid = threadIdx.x;
    int wid = tid >> 5, lane = tid & 31;
    int warp_m = wid >> 1;         // 0..3 -> m offset 32*warp_m
    int warp_n = wid & 1;          // 0..1 -> n offset 64*warp_n
    int bm = blockIdx.y, bn = blockIdx.x;

    const float* Abase = A  + (size_t)bm*128*K;
    const float* Bbase = Bt + (size_t)bn*128*K;

    int lrow = tid >> 1;                 // 0..127 (2 chunks per row per thread pass)
    int lchunk = (tid & 1) * 4;          // float offset of 16B chunk: 0 or 4... 
    // Load pattern: 1024 16B-chunks per tile (128 rows x 8 chunks). Thread t
    // handles chunks {t, t+256, t+512, t+768}: row = cid>>3, kc = cid&7.
    auto load_tile = [&](int buf, int c) {
        const float* Ap = Abase + c*32;
        const float* Bp = Bbase + c*32;
        uint32_t sa = sA_u + (uint32_t)buf*TILE_F*4;
        uint32_t sb = sB_u + (uint32_t)buf*TILE_F*4;
        #pragma unroll
        for (int i = 0; i < 4; i++) {
            int cid = tid + i*256;
            int row = cid >> 3;
            int kc  = cid & 7;
            uint32_t soff = (uint32_t)(row*SROW + kc*4) * 4u;
            cp_async16(sa + soff, Ap + (size_t)row*K + kc*4);
            cp_async16(sb + soff, Bp + (size_t)row*K + kc*4);
        }
    };

    float acc[2][8][4];
    #pragma unroll
    for (int mt = 0; mt < 2; mt++)
        #pragma unroll
        for (int nt = 0; nt < 8; nt++)
            #pragma unroll
            for (int j = 0; j < 4; j++) acc[mt][nt][j] = 0.f;

    int NC = K >> 5;
    load_tile(0, 0);
    cp_commit();

    int r = lane >> 2;      // 0..7
    int cq = lane & 3;      // 0..3

    for (int c = 0; c < NC; c++) {
        int buf = c & 1;
        if (c + 1 < NC) {
            load_tile(buf ^ 1, c + 1);
            cp_commit();
            cp_wait<1>();
        } else {
            cp_wait<0>();
        }
        __syncthreads();

        const float* tA = sA + buf*TILE_F;
        const float* tB = sB + buf*TILE_F;
        #pragma unroll
        for (int kk = 0; kk < 4; kk++) {
            int k0 = kk*8;
            uint32_t af[2][4];
            #pragma unroll
            for (int mt = 0; mt < 2; mt++) {
                int rb = warp_m*32 + mt*16;
                const uint32_t* base = (const uint32_t*)tA;
                af[mt][0] = base[(rb + r    )*SROW + k0 + cq    ];
                af[mt][1] = base[(rb + r + 8)*SROW + k0 + cq    ];
                af[mt][2] = base[(rb + r    )*SROW + k0 + cq + 4];
                af[mt][3] = base[(rb + r + 8)*SROW + k0 + cq + 4];
            }
            #pragma unroll
            for (int nt = 0; nt < 8; nt++) {
                int cb = warp_n*64 + nt*8;
                const uint32_t* base = (const uint32_t*)tB;
                uint32_t b0 = base[(cb + r)*SROW + k0 + cq    ];
                uint32_t b1 = base[(cb + r)*SROW + k0 + cq + 4];
                #pragma unroll
                for (int mt = 0; mt < 2; mt++)
                    mma_tf32(acc[mt][nt][0], acc[mt][nt][1], acc[mt][nt][2], acc[mt][nt][3],
                             af[mt][0], af[mt][1], af[mt][2], af[mt][3], b0, b1);
            }
        }
        __syncthreads();
    }

    // epilogue
    #pragma unroll
    for (int mt = 0; mt < 2; mt++) {
        size_t m0 = (size_t)bm*128 + warp_m*32 + mt*16 + r;
        #pragma unroll
        for (int nt = 0; nt < 8; nt++) {
            int n = bn*128 + warp_n*64 + nt*8 + 2*cq;
            float2 bs = *(const float2*)(bias + n);
            #pragma unroll
            for (int half = 0; half < 2; half++) {
                size_t m = m0 + half*8;
                float vx = acc[mt][nt][half*2 + 0] + bs.x;
                float vy = acc[mt][nt][half*2 + 1] + bs.y;
                if (RESID) {
                    float2 rr = *(const float2*)(Res + m*N + n);
                    vx += rr.x; vy += rr.y;
                }
                if (RELU) {
                    vx = tf32r(fmaxf(vx, 0.f));
                    vy = tf32r(fmaxf(vy, 0.f));
                }
                *(float2*)(C + m*N + n) = make_float2(vx, vy);
            }
        }
    }
    (void)lrow; (void)lchunk;
}

// ---------------- attention scores (fp32) -----------------------------------
__global__ __launch_bounds__(256)
void scores_kernel(const float* __restrict__ q, const float* __restrict__ kmat,
                   const int* __restrict__ x, float* __restrict__ att) {
    int bh = blockIdx.z, b = bh >> 3, h = bh & 7;
    int i0 = blockIdx.y*64, j0 = blockIdx.x*64;
    __shared__ float Qs[64][68];
    __shared__ float Ks[64][68];
    __shared__ int padf[64];
    int tid = threadIdx.x;
    #pragma unroll
    for (int it = 0; it < 4; it++) {
        int lin = tid + it*256;
        int rr = lin >> 4;
        int c4 = (lin & 15) * 4;
        float4 qv = *(const float4*)(q    + (size_t)(b*LL + i0 + rr)*DD + h*DHH + c4);
        Qs[c4+0][rr]=qv.x; Qs[c4+1][rr]=qv.y; Qs[c4+2][rr]=qv.z; Qs[c4+3][rr]=qv.w;
        float4 kv = *(const float4*)(kmat + (size_t)(b*LL + j0 + rr)*DD + h*DHH + c4);
        Ks[c4+0][rr]=kv.x; Ks[c4+1][rr]=kv.y; Ks[c4+2][rr]=kv.z; Ks[c4+3][rr]=kv.w;
    }
    if (tid < 64) padf[tid] = (x[(j0+tid)*BB + b] == 0);
    __syncthreads();
    int ty = tid >> 4, tx = tid & 15;
    float acc[4][4] = {};
    #pragma unroll
    for (int d = 0; d < 64; d++) {
        float4 a = *(const float4*)&Qs[d][ty*4];
        float4 bb = *(const float4*)&Ks[d][tx*4];
        float ra[4] = {a.x,a.y,a.z,a.w};
        float rb[4] = {bb.x,bb.y,bb.z,bb.w};
        #pragma unroll
        for (int i = 0; i < 4; i++)
            #pragma unroll
            for (int j = 0; j < 4; j++)
                acc[i][j] += ra[i]*rb[j];
    }
    const float scale = 0.125f;
    #pragma unroll
    for (int ii = 0; ii < 4; ii++) {
        int i = i0 + ty*4 + ii;
        #pragma unroll
        for (int jj = 0; jj < 4; jj++) {
            int j = j0 + tx*4 + jj;
            float val = padf[tx*4+jj] ? -1e9f : acc[ii][jj]*scale;
            att[((size_t)bh*LL + i)*LL + j] = val;
        }
    }
}

__global__ void softmax_kernel(float* __restrict__ att) {
    __shared__ float red[8];
    float* p = att + (size_t)blockIdx.x * LL;
    float v = p[threadIdx.x];
    float m = block_reduce<true>(v, red);
    float e = __expf(v - m);
    float s = block_reduce<false>(e, red);
    p[threadIdx.x] = e / s;
}

// ctx output rounded to tf32 (feeds WO GEMM)
__global__ __launch_bounds__(256)
void ctx_kernel(const float* __restrict__ att, const float* __restrict__ v,
                float* __restrict__ ctx) {
    int bh = blockIdx.y, b = bh >> 3, h = bh & 7;
    int i0 = blockIdx.x*64;
    __shared__ float Ats[16][68];
    __shared__ float Vs[16][64];
    int tid = threadIdx.x;
    int ty = tid >> 4, tx = tid & 15;
    float acc[4][4] = {};
    for (int k0 = 0; k0 < LL; k0 += 16) {
        {   int rr = tid >> 2, c4 = (tid & 3) * 4;
            float4 a = *(const float4*)(att + ((size_t)bh*LL + i0 + rr)*LL + k0 + c4);
            Ats[c4+0][rr]=a.x; Ats[c4+1][rr]=a.y; Ats[c4+2][rr]=a.z; Ats[c4+3][rr]=a.w; }
        {   int rr = tid >> 4, c4 = (tid & 15) * 4;
            *(float4*)&Vs[rr][c4] = *(const float4*)(v + (size_t)(b*LL + k0 + rr)*DD + h*DHH + c4); }
        __syncthreads();
        #pragma unroll
        for (int kk = 0; kk < 16; kk++) {
            float4 a = *(const float4*)&Ats[kk][ty*4];
            float4 bb = *(const float4*)&Vs[kk][tx*4];
            float ra[4] = {a.x,a.y,a.z,a.w};
            float rb[4] = {bb.x,bb.y,bb.z,bb.w};
            #pragma unroll
            for (int i = 0; i < 4; i++)
                #pragma unroll
                for (int j = 0; j < 4; j++)
                    acc[i][j] += ra[i]*rb[j];
        }
        __syncthreads();
    }
    #pragma unroll
    for (int ii = 0; ii < 4; ii++)
        #pragma unroll
        for (int jj = 0; jj < 4; jj++)
            ctx[(size_t)(b*LL + i0 + ty*4 + ii)*DD + h*DHH + tx*4 + jj] = tf32r(acc[ii][jj]);
}

// ---------------- host driver ------------------------------------------------
extern "C" void kernel_launch(void* const* d_in, const int* in_sizes, int n_in,
                              void* d_out, int out_size) {
    const int*   x           = (const int*)  d_in[0];
    const float* atoms_coord = (const float*)d_in[1];
    const int*   atoms_token = (const int*)  d_in[2];
    const int*   atoms_index = (const int*)  d_in[3];
    const int*   batch_index = (const int*)  d_in[4];
    const float* emb         = (const float*)d_in[5];
    const float* coord_w     = (const float*)d_in[6];
    const float* coord_b     = (const float*)d_in[7];
    const float* rate1       = (const float*)d_in[8];
    const float* rate2       = (const float*)d_in[9];
    const float* ln1_g       = (const float*)d_in[10];
    const float* ln1_b       = (const float*)d_in[11];
    const float* wq          = (const float*)d_in[12];
    const float* bq          = (const float*)d_in[13];
    const float* wk          = (const float*)d_in[14];
    const float* bk          = (const float*)d_in[15];
    const float* wv          = (const float*)d_in[16];
    const float* bv          = (const float*)d_in[17];
    const float* wo          = (const float*)d_in[18];
    const float* bo          = (const float*)d_in[19];
    const float* ln2_g       = (const float*)d_in[20];
    const float* ln2_b       = (const float*)d_in[21];
    const float* w1          = (const float*)d_in[22];
    const float* b1          = (const float*)d_in[23];
    const float* w2          = (const float*)d_in[24];
    const float* b2          = (const float*)d_in[25];
    const float* lnf_g       = (const float*)d_in[26];
    const float* lnf_b       = (const float*)d_in[27];
    float* out = (float*)d_out;

    float *h, *hn, *q, *k, *v, *ctx, *att, *ff, *wt;
    cudaGetSymbolAddress((void**)&h,   g_h);
    cudaGetSymbolAddress((void**)&hn,  g_hn);
    cudaGetSymbolAddress((void**)&q,   g_q);
    cudaGetSymbolAddress((void**)&k,   g_k);
    cudaGetSymbolAddress((void**)&v,   g_v);
    cudaGetSymbolAddress((void**)&ctx, g_ctx);
    cudaGetSymbolAddress((void**)&att, g_att);
    cudaGetSymbolAddress((void**)&ff,  g_ff);
    cudaGetSymbolAddress((void**)&wt,  g_wt);

    cudaFuncSetAttribute(mma_gemm<0,0>, cudaFuncAttributeMaxDynamicSharedMemorySize, SMEM_GEMM);
    cudaFuncSetAttribute(mma_gemm<0,1>, cudaFuncAttributeMaxDynamicSharedMemorySize, SMEM_GEMM);
    cudaFuncSetAttribute(mma_gemm<1,0>, cudaFuncAttributeMaxDynamicSharedMemorySize, SMEM_GEMM);

    // weight transposes (+ tf32 rounding), all layers
    dim3 tb(32, 8);
    for (int l = 0; l < NLAYER; l++) {
        float* base = wt + (size_t)l*WT_LSTRIDE;
        transpose_tf32<<<dim3(16,16), tb>>>(wq + (size_t)l*DD*DD,  base,           DD, DD);
        transpose_tf32<<<dim3(16,16), tb>>>(wk + (size_t)l*DD*DD,  base + 262144,  DD, DD);
        transpose_tf32<<<dim3(16,16), tb>>>(wv + (size_t)l*DD*DD,  base + 524288,  DD, DD);
        transpose_tf32<<<dim3(16,16), tb>>>(wo + (size_t)l*DD*DD,  base + 786432,  DD, DD);
        transpose_tf32<<<dim3(16,64), tb>>>(w1 + (size_t)l*DD*FFD, base + 1048576, DD, FFD);
        transpose_tf32<<<dim3(64,16), tb>>>(w2 + (size_t)l*FFD*DD, base + 2097152, FFD, DD);
    }

    embed_kernel<<<(TT*(DD/4))/256, 256>>>(x, emb, rate1, h);
    atom_kernel<<<NATOM, 128>>>(atoms_coord, atoms_token, atoms_index, batch_index,
                                emb, coord_w, coord_b, rate2, h);

    dim3 gD(DD/128, TT/128);       // (4, 512)
    dim3 gF(FFD/128, TT/128);      // (16, 512)
    dim3 gS(LL/64, LL/64, BB*HH);
    dim3 gC(LL/64, BB*HH);

    for (int l = 0; l < NLAYER; l++) {
        float* base = wt + (size_t)l*WT_LSTRIDE;
        const float* wtq = base;
        const float* wtk = base + 262144;
        const float* wtv = base + 524288;
        const float* wto = base + 786432;
        const float* wt1 = base + 1048576;
        const float* wt2 = base + 2097152;

        ln_kernel<<<TT, 256>>>(h, hn, ln1_g + l*DD, ln1_b + l*DD);
        mma_gemm<0,0><<<gD, 256, SMEM_GEMM>>>(DD, hn, wtq, bq + l*DD, nullptr, q, DD);
        mma_gemm<0,0><<<gD, 256, SMEM_GEMM>>>(DD, hn, wtk, bk + l*DD, nullptr, k, DD);
        mma_gemm<0,0><<<gD, 256, SMEM_GEMM>>>(DD, hn, wtv, bv + l*DD, nullptr, v, DD);
        scores_kernel<<<gS, 256>>>(q, k, x, att);
        softmax_kernel<<<(size_t)BB*HH*LL, 256>>>(att);
        ctx_kernel<<<gC, 256>>>(att, v, ctx);
        mma_gemm<0,1><<<gD, 256, SMEM_GEMM>>>(DD, ctx, wto, bo + l*DD, h, h, DD);
        ln_kernel<<<TT, 256>>>(h, hn, ln2_g + l*DD, ln2_b + l*DD);
        mma_gemm<1,0><<<gF, 256, SMEM_GEMM>>>(DD, hn, wt1, b1 + l*FFD, nullptr, ff, FFD);
        mma_gemm<0,1><<<gD, 256, SMEM_GEMM>>>(FFD, ff, wt2, b2 + l*DD, h, h, DD);
    }
    lnf_kernel<<<TT, 256>>>(h, out, lnf_g, lnf_b);
}

// round 5
// speedup vs baseline: 3.0358x; 1.1881x over previous
#include <cuda_runtime.h>
#include <math.h>
#include <stdint.h>

// Problem constants
#define BB 256
#define LL 256
#define DD 512
#define HH 8
#define DHH 64
#define NLAYER 6
#define FFD 2048
#define TT (BB*LL)          // 65536 tokens
#define NATOM 32768
#define QKVD 1536

// ---------------- scratch (device globals; no allocation allowed) -----------
__device__ float g_h  [(size_t)TT*DD];
__device__ float g_hn [(size_t)TT*DD];
__device__ float g_qkv[(size_t)TT*QKVD];       // 402 MB
__device__ float g_ctx[(size_t)TT*DD];
__device__ float g_ff [(size_t)TT*FFD];        // 536 MB
#define WT_LSTRIDE 3145728
__device__ float g_wt [(size_t)NLAYER*WT_LSTRIDE];   // 75.5 MB
__device__ float g_bqkv[(size_t)NLAYER*QKVD];

// ---------------- small helpers ----------------------------------------------
__device__ __forceinline__ uint32_t smem_u32(const void* p) {
    uint32_t a;
    asm("{ .reg .u64 t; cvta.to.shared.u64 t, %1; cvt.u32.u64 %0, t; }" : "=r"(a) : "l"(p));
    return a;
}
__device__ __forceinline__ float tf32r(float x) {
    uint32_t u; asm("cvt.rn.tf32.f32 %0, %1;" : "=r"(u) : "f"(x));
    return __uint_as_float(u);
}
__device__ __forceinline__ void cp_async16(uint32_t dst, const void* src) {
    asm volatile("cp.async.ca.shared.global [%0], [%1], 16;" :: "r"(dst), "l"(src) : "memory");
}
__device__ __forceinline__ void cp_commit() {
    asm volatile("cp.async.commit_group;" ::: "memory");
}
template<int N>
__device__ __forceinline__ void cp_wait() {
    asm volatile("cp.async.wait_group %0;" :: "n"(N) : "memory");
}
__device__ __forceinline__ void mma_tf32(float& d0, float& d1, float& d2, float& d3,
                                         uint32_t a0, uint32_t a1, uint32_t a2, uint32_t a3,
                                         uint32_t b0, uint32_t b1) {
    asm volatile(
        "mma.sync.aligned.m16n8k8.row.col.f32.tf32.tf32.f32 "
        "{%0,%1,%2,%3}, {%4,%5,%6,%7}, {%8,%9}, {%0,%1,%2,%3};"
        : "+f"(d0), "+f"(d1), "+f"(d2), "+f"(d3)
        : "r"(a0), "r"(a1), "r"(a2), "r"(a3), "r"(b0), "r"(b1));
}

// ---------------- block reduce ----------------------------------------------
template<bool DOMAX>
__device__ __forceinline__ float block_reduce(float v, float* red) {
    __syncthreads();
    #pragma unroll
    for (int o = 16; o; o >>= 1) {
        float other = __shfl_xor_sync(0xffffffffu, v, o);
        v = DOMAX ? fmaxf(v, other) : (v + other);
    }
    if ((threadIdx.x & 31) == 0) red[threadIdx.x >> 5] = v;
    __syncthreads();
    if (threadIdx.x == 0) {
        float t = red[0];
        #pragma unroll
        for (int i = 1; i < 8; i++) t = DOMAX ? fmaxf(t, red[i]) : (t + red[i]);
        red[0] = t;
    }
    __syncthreads();
    return red[0];
}

// ---------------- embedding -------------------------------------------------
__global__ void embed_kernel(const int* __restrict__ x, const float* __restrict__ emb,
                             const float* __restrict__ rate1, float* __restrict__ h) {
    int idx = blockIdx.x * blockDim.x + threadIdx.x;
    int t = idx / (DD/4);
    int c = idx % (DD/4);
    int b = t / LL, l = t % LL;
    int tok = x[l*BB + b];
    float4 e = ((const float4*)(emb + (size_t)tok*DD))[c];
    float r = rate1[0];
    ((float4*)(h + (size_t)t*DD))[c] = make_float4(r*e.x, r*e.y, r*e.z, r*e.w);
}

__global__ void atom_kernel(const float* __restrict__ coord, const int* __restrict__ atok,
                            const int* __restrict__ aidx, const int* __restrict__ bidx,
                            const float* __restrict__ emb, const float* __restrict__ cw,
                            const float* __restrict__ cb, const float* __restrict__ rate2,
                            float* __restrict__ h) {
    int a = blockIdx.x;
    int tok = atok[a];
    float c0 = coord[a*3+0], c1 = coord[a*3+1], c2 = coord[a*3+2];
    size_t row = (size_t)(bidx[a]*LL + aidx[a] + 1) * DD;
    float r = rate2[0];
    for (int i = threadIdx.x; i < DD; i += blockDim.x) {
        float val = emb[(size_t)tok*DD + i] + c0*cw[i] + c1*cw[DD+i] + c2*cw[2*DD+i] + cb[i];
        h[row + i] += r * val;
    }
}

// ---------------- layernorm (output tf32-rounded: feeds tensor GEMMs) -------
__global__ void ln_kernel(const float* __restrict__ in, float* __restrict__ out,
                          const float* __restrict__ g, const float* __restrict__ bt) {
    __shared__ float red[8];
    size_t t = blockIdx.x;
    const float* row = in + t*DD;
    int tid = threadIdx.x;
    float v0 = row[tid], v1 = row[tid+256];
    float mean = block_reduce<false>(v0+v1, red) * (1.0f/DD);
    float d0 = v0-mean, d1 = v1-mean;
    float var = block_reduce<false>(d0*d0+d1*d1, red) * (1.0f/DD);
    float rs = rsqrtf(var + 1e-6f);
    out[t*DD+tid]     = tf32r(d0*rs*g[tid]     + bt[tid]);
    out[t*DD+tid+256] = tf32r(d1*rs*g[tid+256] + bt[tid+256]);
}

// final LN + transpose [B,L,D] -> [L,B,D]
__global__ void lnf_kernel(const float* __restrict__ in, float* __restrict__ out,
                           const float* __restrict__ g, const float* __restrict__ bt) {
    __shared__ float red[8];
    size_t t = blockIdx.x;
    int b = (int)(t / LL), l = (int)(t % LL);
    const float* row = in + t*DD;
    int tid = threadIdx.x;
    float v0 = row[tid], v1 = row[tid+256];
    float mean = block_reduce<false>(v0+v1, red) * (1.0f/DD);
    float d0 = v0-mean, d1 = v1-mean;
    float var = block_reduce<false>(d0*d0+d1*d1, red) * (1.0f/DD);
    float rs = rsqrtf(var + 1e-6f);
    size_t o = (size_t)(l*BB + b) * DD;
    out[o+tid]     = d0*rs*g[tid]     + bt[tid];
    out[o+tid+256] = d1*rs*g[tid+256] + bt[tid+256];
}

// ---------------- weight transpose + tf32 round: Wt[n,k] = tf32(W[k,n]) -----
__global__ void transpose_tf32(const float* __restrict__ W, float* __restrict__ Wt,
                               int K, int N) {
    __shared__ float t[32][33];
    int k0 = blockIdx.x*32, n0 = blockIdx.y*32;
    int tx = threadIdx.x, ty = threadIdx.y;
    for (int i = ty; i < 32; i += 8)
        t[i][tx] = W[(size_t)(k0+i)*N + n0 + tx];
    __syncthreads();
    for (int i = ty; i < 32; i += 8)
        Wt[(size_t)(n0+i)*K + k0 + tx] = tf32r(t[tx][i]);
}

// ---------------- concat QKV bias --------------------------------------------
__global__ void concat_bias(const float* __restrict__ bq, const float* __restrict__ bk,
                            const float* __restrict__ bv, float* __restrict__ bqkv) {
    int l = blockIdx.y;
    int i = blockIdx.x*256 + threadIdx.x;
    float v;
    if (i < 512)       v = bq[l*DD + i];
    else if (i < 1024) v = bk[l*DD + i - 512];
    else               v = bv[l*DD + i - 1024];
    bqkv[(size_t)l*QKVD + i] = v;
}

// ---------------- mma.sync tf32 GEMM: C[M,N] = A[M,K] @ Wt[N,K]^T -----------
#define SROW 36
#define TILE_F (128*SROW)
#define SMEM_GEMM (4*TILE_F*4)     // 73728 bytes

template<int RELU, int RESID>
__global__ void __launch_bounds__(256)
mma_gemm(int K, const float* __restrict__ A, const float* __restrict__ Bt,
         const float* __restrict__ bias, const float* __restrict__ Res,
         float* __restrict__ C, int N) {
    extern __shared__ __align__(16) float dyn[];
    float* sA = dyn;
    float* sB = dyn + 2*TILE_F;
    uint32_t sA_u = smem_u32(sA);
    uint32_t sB_u = smem_u32(sB);

    int tid = threadIdx.x;
    int wid = tid >> 5, lane = tid & 31;
    int warp_m = wid >> 1;
    int warp_n = wid & 1;
    int bm = blockIdx.y, bn = blockIdx.x;

    const float* Abase = A  + (size_t)bm*128*K;
    const float* Bbase = Bt + (size_t)bn*128*K;

    auto load_tile = [&](int buf, int c) {
        const float* Ap = Abase + c*32;
        const float* Bp = Bbase + c*32;
        uint32_t sa = sA_u + (uint32_t)buf*TILE_F*4;
        uint32_t sb = sB_u + (uint32_t)buf*TILE_F*4;
        #pragma unroll
        for (int i = 0; i < 4; i++) {
            int cid = tid + i*256;
            int row = cid >> 3;
            int kc  = cid & 7;
            uint32_t soff = (uint32_t)(row*SROW + kc*4) * 4u;
            cp_async16(sa + soff, Ap + (size_t)row*K + kc*4);
            cp_async16(sb + soff, Bp + (size_t)row*K + kc*4);
        }
    };

    float acc[2][8][4];
    #pragma unroll
    for (int mt = 0; mt < 2; mt++)
        #pragma unroll
        for (int nt = 0; nt < 8; nt++)
            #pragma unroll
            for (int j = 0; j < 4; j++) acc[mt][nt][j] = 0.f;

    int NC = K >> 5;
    load_tile(0, 0);
    cp_commit();

    int r = lane >> 2;
    int cq = lane & 3;

    for (int c = 0; c < NC; c++) {
        int buf = c & 1;
        if (c + 1 < NC) {
            load_tile(buf ^ 1, c + 1);
            cp_commit();
            cp_wait<1>();
        } else {
            cp_wait<0>();
        }
        __syncthreads();

        const float* tA = sA + buf*TILE_F;
        const float* tB = sB + buf*TILE_F;
        #pragma unroll
        for (int kk = 0; kk < 4; kk++) {
            int k0 = kk*8;
            uint32_t af[2][4];
            #pragma unroll
            for (int mt = 0; mt < 2; mt++) {
                int rb = warp_m*32 + mt*16;
                const uint32_t* base = (const uint32_t*)tA;
                af[mt][0] = base[(rb + r    )*SROW + k0 + cq    ];
                af[mt][1] = base[(rb + r + 8)*SROW + k0 + cq    ];
                af[mt][2] = base[(rb + r    )*SROW + k0 + cq + 4];
                af[mt][3] = base[(rb + r + 8)*SROW + k0 + cq + 4];
            }
            #pragma unroll
            for (int nt = 0; nt < 8; nt++) {
                int cb = warp_n*64 + nt*8;
                const uint32_t* base = (const uint32_t*)tB;
                uint32_t b0 = base[(cb + r)*SROW + k0 + cq    ];
                uint32_t b1 = base[(cb + r)*SROW + k0 + cq + 4];
                #pragma unroll
                for (int mt = 0; mt < 2; mt++)
                    mma_tf32(acc[mt][nt][0], acc[mt][nt][1], acc[mt][nt][2], acc[mt][nt][3],
                             af[mt][0], af[mt][1], af[mt][2], af[mt][3], b0, b1);
            }
        }
        __syncthreads();
    }

    #pragma unroll
    for (int mt = 0; mt < 2; mt++) {
        size_t m0 = (size_t)bm*128 + warp_m*32 + mt*16 + r;
        #pragma unroll
        for (int nt = 0; nt < 8; nt++) {
            int n = bn*128 + warp_n*64 + nt*8 + 2*cq;
            float2 bs = *(const float2*)(bias + n);
            #pragma unroll
            for (int half = 0; half < 2; half++) {
                size_t m = m0 + half*8;
                float vx = acc[mt][nt][half*2 + 0] + bs.x;
                float vy = acc[mt][nt][half*2 + 1] + bs.y;
                if (RESID) {
                    float2 rr = *(const float2*)(Res + m*N + n);
                    vx += rr.x; vy += rr.y;
                }
                if (RELU) {
                    vx = tf32r(fmaxf(vx, 0.f));
                    vy = tf32r(fmaxf(vy, 0.f));
                }
                *(float2*)(C + m*N + n) = make_float2(vx, vy);
            }
        }
    }
}

// ---------------- fused flash attention --------------------------------------
// grid (L/64, B*H), 256 threads. Q tile 64 rows x full K loop (4 tiles of 64).
// S and P@V in fp32 scalar; online softmax. K smem buffer reused for P.
// ctx output tf32-rounded (feeds WO GEMM).
#define FA_STRIDE 68
#define FA_TILE (64*FA_STRIDE)
#define SMEM_FLASH (3*FA_TILE*4 + 64*4)    // Qs,KP,Vs + padf = 52480 bytes

__global__ void __launch_bounds__(256)
flash_kernel(const float* __restrict__ qkv, const int* __restrict__ x,
             float* __restrict__ ctx) {
    extern __shared__ __align__(16) float fdyn[];
    float* Qs = fdyn;                 // [d][i] 64x68
    float* KP = fdyn + FA_TILE;       // K: [d][j]; later P: [i][j]
    float* Vs = fdyn + 2*FA_TILE;     // [j][d] 64x68
    int* padf = (int*)(fdyn + 3*FA_TILE);

    int bh = blockIdx.y, b = bh >> 3, h = bh & 7;
    int i0 = blockIdx.x * 64;
    int tid = threadIdx.x;
    int ty = tid >> 4, tx = tid & 15;

    // load Q tile -> Qs[d][i]
    #pragma unroll
    for (int it = 0; it < 4; it++) {
        int lin = tid + it*256;
        int rr = lin >> 4;
        int c4 = (lin & 15) * 4;
        float4 qv = *(const float4*)(qkv + (size_t)(b*LL + i0 + rr)*QKVD + h*DHH + c4);
        Qs[(c4+0)*FA_STRIDE + rr] = qv.x; Qs[(c4+1)*FA_STRIDE + rr] = qv.y;
        Qs[(c4+2)*FA_STRIDE + rr] = qv.z; Qs[(c4+3)*FA_STRIDE + rr] = qv.w;
    }

    float Oa[4][4] = {};
    float mrun[4] = {-1e30f, -1e30f, -1e30f, -1e30f};
    float srun[4] = {};

    for (int kt = 0; kt < 4; kt++) {
        int j0 = kt * 64;
        __syncthreads();   // Q ready (kt=0) / prior P reads done (kt>0)
        // load K -> KP[d][j], V -> Vs[j][d], pad flags
        #pragma unroll
        for (int it = 0; it < 4; it++) {
            int lin = tid + it*256;
            int rr = lin >> 4;
            int c4 = (lin & 15) * 4;
            const float* rowp = qkv + (size_t)(b*LL + j0 + rr)*QKVD + h*DHH;
            float4 kv = *(const float4*)(rowp + 512 + c4);
            KP[(c4+0)*FA_STRIDE + rr] = kv.x; KP[(c4+1)*FA_STRIDE + rr] = kv.y;
            KP[(c4+2)*FA_STRIDE + rr] = kv.z; KP[(c4+3)*FA_STRIDE + rr] = kv.w;
            float4 vv = *(const float4*)(rowp + 1024 + c4);
            *(float4*)&Vs[rr*FA_STRIDE + c4] = vv;
        }
        if (tid < 64) padf[tid] = (x[(j0 + tid)*BB + b] == 0);
        __syncthreads();

        // S = scale * Q K^T, masked
        float S[4][4] = {};
        #pragma unroll
        for (int d = 0; d < 64; d++) {
            float4 a  = *(const float4*)&Qs[d*FA_STRIDE + ty*4];
            float4 bb = *(const float4*)&KP[d*FA_STRIDE + tx*4];
            float ra[4] = {a.x, a.y, a.z, a.w};
            float rb[4] = {bb.x, bb.y, bb.z, bb.w};
            #pragma unroll
            for (int i = 0; i < 4; i++)
                #pragma unroll
                for (int j = 0; j < 4; j++)
                    S[i][j] += ra[i]*rb[j];
        }
        int pf[4];
        #pragma unroll
        for (int j = 0; j < 4; j++) pf[j] = padf[tx*4 + j];
        #pragma unroll
        for (int i = 0; i < 4; i++)
            #pragma unroll
            for (int j = 0; j < 4; j++)
                S[i][j] = pf[j] ? -1e9f : S[i][j]*0.125f;

        // online softmax per row (reduce across the 16-lane tx group)
        #pragma unroll
        for (int i = 0; i < 4; i++) {
            float tm = fmaxf(fmaxf(S[i][0], S[i][1]), fmaxf(S[i][2], S[i][3]));
            #pragma unroll
            for (int o = 1; o < 16; o <<= 1)
                tm = fmaxf(tm, __shfl_xor_sync(0xffffffffu, tm, o));
            float mnew = fmaxf(mrun[i], tm);
            float corr = __expf(mrun[i] - mnew);
            float rowsum = 0.f;
            #pragma unroll
            for (int j = 0; j < 4; j++) {
                float p = __expf(S[i][j] - mnew);
                S[i][j] = p;
                rowsum += p;
            }
            #pragma unroll
            for (int o = 1; o < 16; o <<= 1)
                rowsum += __shfl_xor_sync(0xffffffffu, rowsum, o);
            srun[i] = srun[i]*corr + rowsum;
            mrun[i] = mnew;
            #pragma unroll
            for (int j = 0; j < 4; j++) Oa[i][j] *= corr;
        }

        __syncthreads();   // all K reads done before P overwrites KP
        #pragma unroll
        for (int i = 0; i < 4; i++)
            #pragma unroll
            for (int j = 0; j < 4; j++)
                KP[(ty*4 + i)*FA_STRIDE + tx*4 + j] = S[i][j];
        __syncthreads();

        // O += P @ V
        #pragma unroll 8
        for (int j = 0; j < 64; j++) {
            float4 vv = *(const float4*)&Vs[j*FA_STRIDE + tx*4];
            float p0 = KP[(ty*4+0)*FA_STRIDE + j];
            float p1 = KP[(ty*4+1)*FA_STRIDE + j];
            float p2 = KP[(ty*4+2)*FA_STRIDE + j];
            float p3 = KP[(ty*4+3)*FA_STRIDE + j];
            Oa[0][0] += p0*vv.x; Oa[0][1] += p0*vv.y; Oa[0][2] += p0*vv.z; Oa[0][3] += p0*vv.w;
            Oa[1][0] += p1*vv.x; Oa[1][1] += p1*vv.y; Oa[1][2] += p1*vv.z; Oa[1][3] += p1*vv.w;
            Oa[2][0] += p2*vv.x; Oa[2][1] += p2*vv.y; Oa[2][2] += p2*vv.z; Oa[2][3] += p2*vv.w;
            Oa[3][0] += p3*vv.x; Oa[3][1] += p3*vv.y; Oa[3][2] += p3*vv.z; Oa[3][3] += p3*vv.w;
        }
    }

    #pragma unroll
    for (int i = 0; i < 4; i++) {
        float inv = 1.0f / srun[i];
        size_t row = (size_t)(b*LL + i0 + ty*4 + i)*DD + h*DHH + tx*4;
        ctx[row+0] = tf32r(Oa[i][0]*inv);
        ctx[row+1] = tf32r(Oa[i][1]*inv);
        ctx[row+2] = tf32r(Oa[i][2]*inv);
        ctx[row+3] = tf32r(Oa[i][3]*inv);
    }
}

// ---------------- host driver ------------------------------------------------
extern "C" void kernel_launch(void* const* d_in, const int* in_sizes, int n_in,
                              void* d_out, int out_size) {
    const int*   x           = (const int*)  d_in[0];
    const float* atoms_coord = (const float*)d_in[1];
    const int*   atoms_token = (const int*)  d_in[2];
    const int*   atoms_index = (const int*)  d_in[3];
    const int*   batch_index = (const int*)  d_in[4];
    const float* emb         = (const float*)d_in[5];
    const float* coord_w     = (const float*)d_in[6];
    const float* coord_b     = (const float*)d_in[7];
    const float* rate1       = (const float*)d_in[8];
    const float* rate2       = (const float*)d_in[9];
    const float* ln1_g       = (const float*)d_in[10];
    const float* ln1_b       = (const float*)d_in[11];
    const float* wq          = (const float*)d_in[12];
    const float* bq          = (const float*)d_in[13];
    const float* wk          = (const float*)d_in[14];
    const float* bk          = (const float*)d_in[15];
    const float* wv          = (const float*)d_in[16];
    const float* bv          = (const float*)d_in[17];
    const float* wo          = (const float*)d_in[18];
    const float* bo          = (const float*)d_in[19];
    const float* ln2_g       = (const float*)d_in[20];
    const float* ln2_b       = (const float*)d_in[21];
    const float* w1          = (const float*)d_in[22];
    const float* b1          = (const float*)d_in[23];
    const float* w2          = (const float*)d_in[24];
    const float* b2          = (const float*)d_in[25];
    const float* lnf_g       = (const float*)d_in[26];
    const float* lnf_b       = (const float*)d_in[27];
    float* out = (float*)d_out;

    float *h, *hn, *qkv, *ctx, *ff, *wt, *bqkv;
    cudaGetSymbolAddress((void**)&h,    g_h);
    cudaGetSymbolAddress((void**)&hn,   g_hn);
    cudaGetSymbolAddress((void**)&qkv,  g_qkv);
    cudaGetSymbolAddress((void**)&ctx,  g_ctx);
    cudaGetSymbolAddress((void**)&ff,   g_ff);
    cudaGetSymbolAddress((void**)&wt,   g_wt);
    cudaGetSymbolAddress((void**)&bqkv, g_bqkv);

    cudaFuncSetAttribute(mma_gemm<0,0>, cudaFuncAttributeMaxDynamicSharedMemorySize, SMEM_GEMM);
    cudaFuncSetAttribute(mma_gemm<0,1>, cudaFuncAttributeMaxDynamicSharedMemorySize, SMEM_GEMM);
    cudaFuncSetAttribute(mma_gemm<1,0>, cudaFuncAttributeMaxDynamicSharedMemorySize, SMEM_GEMM);
    cudaFuncSetAttribute(flash_kernel,  cudaFuncAttributeMaxDynamicSharedMemorySize, SMEM_FLASH);

    // weight transposes (+ tf32 rounding): Wt_qkv rows 0..511 = wq, 512.. = wk, 1024.. = wv
    dim3 tb(32, 8);
    for (int l = 0; l < NLAYER; l++) {
        float* base = wt + (size_t)l*WT_LSTRIDE;
        transpose_tf32<<<dim3(16,16), tb>>>(wq + (size_t)l*DD*DD,  base,           DD, DD);
        transpose_tf32<<<dim3(16,16), tb>>>(wk + (size_t)l*DD*DD,  base + 262144,  DD, DD);
        transpose_tf32<<<dim3(16,16), tb>>>(wv + (size_t)l*DD*DD,  base + 524288,  DD, DD);
        transpose_tf32<<<dim3(16,16), tb>>>(wo + (size_t)l*DD*DD,  base + 786432,  DD, DD);
        transpose_tf32<<<dim3(16,64), tb>>>(w1 + (size_t)l*DD*FFD, base + 1048576, DD, FFD);
        transpose_tf32<<<dim3(64,16), tb>>>(w2 + (size_t)l*FFD*DD, base + 2097152, FFD, DD);
    }
    concat_bias<<<dim3(6, NLAYER), 256>>>(bq, bk, bv, bqkv);

    embed_kernel<<<(TT*(DD/4))/256, 256>>>(x, emb, rate1, h);
    atom_kernel<<<NATOM, 128>>>(atoms_coord, atoms_token, atoms_index, batch_index,
                                emb, coord_w, coord_b, rate2, h);

    dim3 gD(DD/128, TT/128);       // (4, 512)
    dim3 gQKV(QKVD/128, TT/128);   // (12, 512)
    dim3 gF(FFD/128, TT/128);      // (16, 512)
    dim3 gFA(LL/64, BB*HH);        // (4, 2048)

    for (int l = 0; l < NLAYER; l++) {
        float* base = wt + (size_t)l*WT_LSTRIDE;
        const float* wtqkv = base;
        const float* wto = base + 786432;
        const float* wt1 = base + 1048576;
        const float* wt2 = base + 2097152;

        ln_kernel<<<TT, 256>>>(h, hn, ln1_g + l*DD, ln1_b + l*DD);
        mma_gemm<0,0><<<gQKV, 256, SMEM_GEMM>>>(DD, hn, wtqkv, bqkv + (size_t)l*QKVD,
                                                nullptr, qkv, QKVD);
        flash_kernel<<<gFA, 256, SMEM_FLASH>>>(qkv, x, ctx);
        mma_gemm<0,1><<<gD, 256, SMEM_GEMM>>>(DD, ctx, wto, bo + l*DD, h, h, DD);
        ln_kernel<<<TT, 256>>>(h, hn, ln2_g + l*DD, ln2_b + l*DD);
        mma_gemm<1,0><<<gF, 256, SMEM_GEMM>>>(DD, hn, wt1, b1 + l*FFD, nullptr, ff, FFD);
        mma_gemm<0,1><<<gD, 256, SMEM_GEMM>>>(FFD, ff, wt2, b2 + l*DD, h, h, DD);
    }
    lnf_kernel<<<TT, 256>>>(h, out, lnf_g, lnf_b);
}

// round 6
// speedup vs baseline: 4.4501x; 1.4659x over previous
#include <cuda_runtime.h>
#include <cuda_fp16.h>
#include <math.h>
#include <stdint.h>

// Problem constants
#define BB 256
#define LL 256
#define DD 512
#define HH 8
#define DHH 64
#define NLAYER 6
#define FFD 2048
#define TT (BB*LL)          // 65536 tokens
#define NATOM 32768
#define QKVD 1536

// ---------------- scratch (device globals; no allocation allowed) -----------
__device__ float  g_h  [(size_t)TT*DD];
__device__ __half g_hn [(size_t)TT*DD];
__device__ float  g_qkv[(size_t)TT*QKVD];      // 402 MB
__device__ __half g_ctx[(size_t)TT*DD];
__device__ __half g_ff [(size_t)TT*FFD];       // 268 MB
#define WT_LSTRIDE 3145728
__device__ __half g_wt [(size_t)NLAYER*WT_LSTRIDE];  // 37.7 MB
__device__ float  g_bqkv[(size_t)NLAYER*QKVD];

// ---------------- small helpers ----------------------------------------------
__device__ __forceinline__ uint32_t smem_u32(const void* p) {
    uint32_t a;
    asm("{ .reg .u64 t; cvta.to.shared.u64 t, %1; cvt.u32.u64 %0, t; }" : "=r"(a) : "l"(p));
    return a;
}
__device__ __forceinline__ void cp_async16(uint32_t dst, const void* src) {
    asm volatile("cp.async.ca.shared.global [%0], [%1], 16;" :: "r"(dst), "l"(src) : "memory");
}
__device__ __forceinline__ void cp_commit() {
    asm volatile("cp.async.commit_group;" ::: "memory");
}
template<int N>
__device__ __forceinline__ void cp_wait() {
    asm volatile("cp.async.wait_group %0;" :: "n"(N) : "memory");
}
__device__ __forceinline__ void mma_f16(float& d0, float& d1, float& d2, float& d3,
                                        uint32_t a0, uint32_t a1, uint32_t a2, uint32_t a3,
                                        uint32_t b0, uint32_t b1) {
    asm volatile(
        "mma.sync.aligned.m16n8k16.row.col.f32.f16.f16.f32 "
        "{%0,%1,%2,%3}, {%4,%5,%6,%7}, {%8,%9}, {%0,%1,%2,%3};"
        : "+f"(d0), "+f"(d1), "+f"(d2), "+f"(d3)
        : "r"(a0), "r"(a1), "r"(a2), "r"(a3), "r"(b0), "r"(b1));
}
// output store helpers
__device__ __forceinline__ void store_pair(float* p, float vx, float vy) {
    *(float2*)p = make_float2(vx, vy);
}
__device__ __forceinline__ void store_pair(__half* p, float vx, float vy) {
    *(__half2*)p = __floats2half2_rn(vx, vy);
}

// ---------------- block reduce ----------------------------------------------
template<bool DOMAX>
__device__ __forceinline__ float block_reduce(float v, float* red) {
    __syncthreads();
    #pragma unroll
    for (int o = 16; o; o >>= 1) {
        float other = __shfl_xor_sync(0xffffffffu, v, o);
        v = DOMAX ? fmaxf(v, other) : (v + other);
    }
    if ((threadIdx.x & 31) == 0) red[threadIdx.x >> 5] = v;
    __syncthreads();
    if (threadIdx.x == 0) {
        float t = red[0];
        #pragma unroll
        for (int i = 1; i < 8; i++) t = DOMAX ? fmaxf(t, red[i]) : (t + red[i]);
        red[0] = t;
    }
    __syncthreads();
    return red[0];
}

// ---------------- embedding -------------------------------------------------
__global__ void embed_kernel(const int* __restrict__ x, const float* __restrict__ emb,
                             const float* __restrict__ rate1, float* __restrict__ h) {
    int idx = blockIdx.x * blockDim.x + threadIdx.x;
    int t = idx / (DD/4);
    int c = idx % (DD/4);
    int b = t / LL, l = t % LL;
    int tok = x[l*BB + b];
    float4 e = ((const float4*)(emb + (size_t)tok*DD))[c];
    float r = rate1[0];
    ((float4*)(h + (size_t)t*DD))[c] = make_float4(r*e.x, r*e.y, r*e.z, r*e.w);
}

__global__ void atom_kernel(const float* __restrict__ coord, const int* __restrict__ atok,
                            const int* __restrict__ aidx, const int* __restrict__ bidx,
                            const float* __restrict__ emb, const float* __restrict__ cw,
                            const float* __restrict__ cb, const float* __restrict__ rate2,
                            float* __restrict__ h) {
    int a = blockIdx.x;
    int tok = atok[a];
    float c0 = coord[a*3+0], c1 = coord[a*3+1], c2 = coord[a*3+2];
    size_t row = (size_t)(bidx[a]*LL + aidx[a] + 1) * DD;
    float r = rate2[0];
    for (int i = threadIdx.x; i < DD; i += blockDim.x) {
        float val = emb[(size_t)tok*DD + i] + c0*cw[i] + c1*cw[DD+i] + c2*cw[2*DD+i] + cb[i];
        h[row + i] += r * val;
    }
}

// ---------------- layernorm (half output: feeds fp16 tensor GEMMs) ----------
__global__ void ln_kernel(const float* __restrict__ in, __half* __restrict__ out,
                          const float* __restrict__ g, const float* __restrict__ bt) {
    __shared__ float red[8];
    size_t t = blockIdx.x;
    const float* row = in + t*DD;
    int tid = threadIdx.x;
    float v0 = row[tid], v1 = row[tid+256];
    float mean = block_reduce<false>(v0+v1, red) * (1.0f/DD);
    float d0 = v0-mean, d1 = v1-mean;
    float var = block_reduce<false>(d0*d0+d1*d1, red) * (1.0f/DD);
    float rs = rsqrtf(var + 1e-6f);
    out[t*DD+tid]     = __float2half(d0*rs*g[tid]     + bt[tid]);
    out[t*DD+tid+256] = __float2half(d1*rs*g[tid+256] + bt[tid+256]);
}

// final LN + transpose [B,L,D] -> [L,B,D]
__global__ void lnf_kernel(const float* __restrict__ in, float* __restrict__ out,
                           const float* __restrict__ g, const float* __restrict__ bt) {
    __shared__ float red[8];
    size_t t = blockIdx.x;
    int b = (int)(t / LL), l = (int)(t % LL);
    const float* row = in + t*DD;
    int tid = threadIdx.x;
    float v0 = row[tid], v1 = row[tid+256];
    float mean = block_reduce<false>(v0+v1, red) * (1.0f/DD);
    float d0 = v0-mean, d1 = v1-mean;
    float var = block_reduce<false>(d0*d0+d1*d1, red) * (1.0f/DD);
    float rs = rsqrtf(var + 1e-6f);
    size_t o = (size_t)(l*BB + b) * DD;
    out[o+tid]     = d0*rs*g[tid]     + bt[tid];
    out[o+tid+256] = d1*rs*g[tid+256] + bt[tid+256];
}

// ---------------- weight transpose + fp16 convert: Wt[n,k] = h(W[k,n]) ------
__global__ void transpose_f16(const float* __restrict__ W, __half* __restrict__ Wt,
                              int K, int N) {
    __shared__ float t[32][33];
    int k0 = blockIdx.x*32, n0 = blockIdx.y*32;
    int tx = threadIdx.x, ty = threadIdx.y;
    for (int i = ty; i < 32; i += 8)
        t[i][tx] = W[(size_t)(k0+i)*N + n0 + tx];
    __syncthreads();
    for (int i = ty; i < 32; i += 8)
        Wt[(size_t)(n0+i)*K + k0 + tx] = __float2half(t[tx][i]);
}

// ---------------- concat QKV bias --------------------------------------------
__global__ void concat_bias(const float* __restrict__ bq, const float* __restrict__ bk,
                            const float* __restrict__ bv, float* __restrict__ bqkv) {
    int l = blockIdx.y;
    int i = blockIdx.x*256 + threadIdx.x;
    float v;
    if (i < 512)       v = bq[l*DD + i];
    else if (i < 1024) v = bk[l*DD + i - 512];
    else               v = bv[l*DD + i - 1024];
    bqkv[(size_t)l*QKVD + i] = v;
}

// ---------------- fp16 mma GEMM: C[M,N] = A[M,K] @ Wt[N,K]^T + bias ----------
// BM=BN=128, BK=64 halves, 256 threads = 8 warps (4 M x 2 N), warp tile 32x64.
// SMEM rows padded to 72 halves (144B) -> conflict-free 4B fragment loads.
#define SROWH 72
#define TILEH (128*SROWH)              // halves per tile buffer
#define SMEM_GEMM (4*TILEH*2)          // 73728 bytes

template<int RELU, int RESID, typename OutT>
__global__ void __launch_bounds__(256)
mma_gemm(int K, const __half* __restrict__ A, const __half* __restrict__ Bt,
         const float* __restrict__ bias, const float* __restrict__ Res,
         OutT* __restrict__ C, int N) {
    extern __shared__ __align__(16) __half hdyn[];
    __half* sA = hdyn;
    __half* sB = hdyn + 2*TILEH;
    uint32_t sA_u = smem_u32(sA);
    uint32_t sB_u = smem_u32(sB);

    int tid = threadIdx.x;
    int wid = tid >> 5, lane = tid & 31;
    int warp_m = wid >> 1;
    int warp_n = wid & 1;
    int bm = blockIdx.y, bn = blockIdx.x;

    const __half* Abase = A  + (size_t)bm*128*K;
    const __half* Bbase = Bt + (size_t)bn*128*K;

    // per tile: 128 rows x 64 halves = 1024 x 16B chunks /256thr = 4 each
    auto load_tile = [&](int buf, int c) {
        const __half* Ap = Abase + c*64;
        const __half* Bp = Bbase + c*64;
        uint32_t sa = sA_u + (uint32_t)buf*TILEH*2;
        uint32_t sb = sB_u + (uint32_t)buf*TILEH*2;
        #pragma unroll
        for (int i = 0; i < 4; i++) {
            int cid = tid + i*256;
            int row = cid >> 3;
            int kc  = cid & 7;
            uint32_t soff = (uint32_t)(row*144 + kc*16);
            cp_async16(sa + soff, Ap + (size_t)row*K + kc*8);
            cp_async16(sb + soff, Bp + (size_t)row*K + kc*8);
        }
    };

    float acc[2][8][4];
    #pragma unroll
    for (int mt = 0; mt < 2; mt++)
        #pragma unroll
        for (int nt = 0; nt < 8; nt++)
            #pragma unroll
            for (int j = 0; j < 4; j++) acc[mt][nt][j] = 0.f;

    int NC = K >> 6;
    load_tile(0, 0);
    cp_commit();

    int r = lane >> 2;      // 0..7
    int cq = lane & 3;      // 0..3

    for (int c = 0; c < NC; c++) {
        int buf = c & 1;
        if (c + 1 < NC) {
            load_tile(buf ^ 1, c + 1);
            cp_commit();
            cp_wait<1>();
        } else {
            cp_wait<0>();
        }
        __syncthreads();

        const __half* tA = sA + buf*TILEH;
        const __half* tB = sB + buf*TILEH;
        #pragma unroll
        for (int kk = 0; kk < 4; kk++) {
            int k0 = kk*16;
            uint32_t af[2][4];
            #pragma unroll
            for (int mt = 0; mt < 2; mt++) {
                int base = (warp_m*32 + mt*16 + r)*SROWH + k0 + 2*cq;
                af[mt][0] = *(const uint32_t*)&tA[base];
                af[mt][1] = *(const uint32_t*)&tA[base + 8*SROWH];
                af[mt][2] = *(const uint32_t*)&tA[base + 8];
                af[mt][3] = *(const uint32_t*)&tA[base + 8*SROWH + 8];
            }
            #pragma unroll
            for (int nt = 0; nt < 8; nt++) {
                int nb = (warp_n*64 + nt*8 + r)*SROWH + k0 + 2*cq;
                uint32_t b0 = *(const uint32_t*)&tB[nb];
                uint32_t b1 = *(const uint32_t*)&tB[nb + 8];
                #pragma unroll
                for (int mt = 0; mt < 2; mt++)
                    mma_f16(acc[mt][nt][0], acc[mt][nt][1], acc[mt][nt][2], acc[mt][nt][3],
                            af[mt][0], af[mt][1], af[mt][2], af[mt][3], b0, b1);
            }
        }
        __syncthreads();
    }

    // epilogue: d0,d1 -> (row r, cols 2cq,2cq+1); d2,d3 -> (row r+8)
    #pragma unroll
    for (int mt = 0; mt < 2; mt++) {
        size_t m0 = (size_t)bm*128 + warp_m*32 + mt*16 + r;
        #pragma unroll
        for (int nt = 0; nt < 8; nt++) {
            int n = bn*128 + warp_n*64 + nt*8 + 2*cq;
            float2 bs = *(const float2*)(bias + n);
            #pragma unroll
            for (int half_i = 0; half_i < 2; half_i++) {
                size_t m = m0 + half_i*8;
                float vx = acc[mt][nt][half_i*2 + 0] + bs.x;
                float vy = acc[mt][nt][half_i*2 + 1] + bs.y;
                if (RESID) {
                    float2 rr = *(const float2*)(Res + m*N + n);
                    vx += rr.x; vy += rr.y;
                }
                if (RELU) {
                    vx = fmaxf(vx, 0.f);
                    vy = fmaxf(vy, 0.f);
                }
                store_pair(C + m*N + n, vx, vy);
            }
        }
    }
}

// ---------------- fused flash attention --------------------------------------
// grid (L/64, B*H), 256 threads. fp32 scalar math; half ctx output.
#define FA_STRIDE 68
#define FA_TILE (64*FA_STRIDE)
#define SMEM_FLASH (3*FA_TILE*4 + 64*4)    // 52480 bytes

__global__ void __launch_bounds__(256)
flash_kernel(const float* __restrict__ qkv, const int* __restrict__ x,
             __half* __restrict__ ctx) {
    extern __shared__ __align__(16) float fdyn[];
    float* Qs = fdyn;                 // [d][i] 64x68
    float* KP = fdyn + FA_TILE;       // K: [d][j]; later P: [i][j]
    float* Vs = fdyn + 2*FA_TILE;     // [j][d] 64x68
    int* padf = (int*)(fdyn + 3*FA_TILE);

    int bh = blockIdx.y, b = bh >> 3, h = bh & 7;
    int i0 = blockIdx.x * 64;
    int tid = threadIdx.x;
    int ty = tid >> 4, tx = tid & 15;

    #pragma unroll
    for (int it = 0; it < 4; it++) {
        int lin = tid + it*256;
        int rr = lin >> 4;
        int c4 = (lin & 15) * 4;
        float4 qv = *(const float4*)(qkv + (size_t)(b*LL + i0 + rr)*QKVD + h*DHH + c4);
        Qs[(c4+0)*FA_STRIDE + rr] = qv.x; Qs[(c4+1)*FA_STRIDE + rr] = qv.y;
        Qs[(c4+2)*FA_STRIDE + rr] = qv.z; Qs[(c4+3)*FA_STRIDE + rr] = qv.w;
    }

    float Oa[4][4] = {};
    float mrun[4] = {-1e30f, -1e30f, -1e30f, -1e30f};
    float srun[4] = {};

    for (int kt = 0; kt < 4; kt++) {
        int j0 = kt * 64;
        __syncthreads();
        #pragma unroll
        for (int it = 0; it < 4; it++) {
            int lin = tid + it*256;
            int rr = lin >> 4;
            int c4 = (lin & 15) * 4;
            const float* rowp = qkv + (size_t)(b*LL + j0 + rr)*QKVD + h*DHH;
            float4 kv = *(const float4*)(rowp + 512 + c4);
            KP[(c4+0)*FA_STRIDE + rr] = kv.x; KP[(c4+1)*FA_STRIDE + rr] = kv.y;
            KP[(c4+2)*FA_STRIDE + rr] = kv.z; KP[(c4+3)*FA_STRIDE + rr] = kv.w;
            float4 vv = *(const float4*)(rowp + 1024 + c4);
            *(float4*)&Vs[rr*FA_STRIDE + c4] = vv;
        }
        if (tid < 64) padf[tid] = (x[(j0 + tid)*BB + b] == 0);
        __syncthreads();

        float S[4][4] = {};
        #pragma unroll
        for (int d = 0; d < 64; d++) {
            float4 a  = *(const float4*)&Qs[d*FA_STRIDE + ty*4];
            float4 bb = *(const float4*)&KP[d*FA_STRIDE + tx*4];
            float ra[4] = {a.x, a.y, a.z, a.w};
            float rb[4] = {bb.x, bb.y, bb.z, bb.w};
            #pragma unroll
            for (int i = 0; i < 4; i++)
                #pragma unroll
                for (int j = 0; j < 4; j++)
                    S[i][j] += ra[i]*rb[j];
        }
        int pf[4];
        #pragma unroll
        for (int j = 0; j < 4; j++) pf[j] = padf[tx*4 + j];
        #pragma unroll
        for (int i = 0; i < 4; i++)
            #pragma unroll
            for (int j = 0; j < 4; j++)
                S[i][j] = pf[j] ? -1e9f : S[i][j]*0.125f;

        #pragma unroll
        for (int i = 0; i < 4; i++) {
            float tm = fmaxf(fmaxf(S[i][0], S[i][1]), fmaxf(S[i][2], S[i][3]));
            #pragma unroll
            for (int o = 1; o < 16; o <<= 1)
                tm = fmaxf(tm, __shfl_xor_sync(0xffffffffu, tm, o));
            float mnew = fmaxf(mrun[i], tm);
            float corr = __expf(mrun[i] - mnew);
            float rowsum = 0.f;
            #pragma unroll
            for (int j = 0; j < 4; j++) {
                float p = __expf(S[i][j] - mnew);
                S[i][j] = p;
                rowsum += p;
            }
            #pragma unroll
            for (int o = 1; o < 16; o <<= 1)
                rowsum += __shfl_xor_sync(0xffffffffu, rowsum, o);
            srun[i] = srun[i]*corr + rowsum;
            mrun[i] = mnew;
            #pragma unroll
            for (int j = 0; j < 4; j++) Oa[i][j] *= corr;
        }

        __syncthreads();
        #pragma unroll
        for (int i = 0; i < 4; i++)
            #pragma unroll
            for (int j = 0; j < 4; j++)
                KP[(ty*4 + i)*FA_STRIDE + tx*4 + j] = S[i][j];
        __syncthreads();

        #pragma unroll 8
        for (int j = 0; j < 64; j++) {
            float4 vv = *(const float4*)&Vs[j*FA_STRIDE + tx*4];
            float p0 = KP[(ty*4+0)*FA_STRIDE + j];
            float p1 = KP[(ty*4+1)*FA_STRIDE + j];
            float p2 = KP[(ty*4+2)*FA_STRIDE + j];
            float p3 = KP[(ty*4+3)*FA_STRIDE + j];
            Oa[0][0] += p0*vv.x; Oa[0][1] += p0*vv.y; Oa[0][2] += p0*vv.z; Oa[0][3] += p0*vv.w;
            Oa[1][0] += p1*vv.x; Oa[1][1] += p1*vv.y; Oa[1][2] += p1*vv.z; Oa[1][3] += p1*vv.w;
            Oa[2][0] += p2*vv.x; Oa[2][1] += p2*vv.y; Oa[2][2] += p2*vv.z; Oa[2][3] += p2*vv.w;
            Oa[3][0] += p3*vv.x; Oa[3][1] += p3*vv.y; Oa[3][2] += p3*vv.z; Oa[3][3] += p3*vv.w;
        }
    }

    #pragma unroll
    for (int i = 0; i < 4; i++) {
        float inv = 1.0f / srun[i];
        size_t row = (size_t)(b*LL + i0 + ty*4 + i)*DD + h*DHH + tx*4;
        __half2* p = (__half2*)(ctx + row);
        p[0] = __floats2half2_rn(Oa[i][0]*inv, Oa[i][1]*inv);
        p[1] = __floats2half2_rn(Oa[i][2]*inv, Oa[i][3]*inv);
    }
}

// ---------------- host driver ------------------------------------------------
extern "C" void kernel_launch(void* const* d_in, const int* in_sizes, int n_in,
                              void* d_out, int out_size) {
    const int*   x           = (const int*)  d_in[0];
    const float* atoms_coord = (const float*)d_in[1];
    const int*   atoms_token = (const int*)  d_in[2];
    const int*   atoms_index = (const int*)  d_in[3];
    const int*   batch_index = (const int*)  d_in[4];
    const float* emb         = (const float*)d_in[5];
    const float* coord_w     = (const float*)d_in[6];
    const float* coord_b     = (const float*)d_in[7];
    const float* rate1       = (const float*)d_in[8];
    const float* rate2       = (const float*)d_in[9];
    const float* ln1_g       = (const float*)d_in[10];
    const float* ln1_b       = (const float*)d_in[11];
    const float* wq          = (const float*)d_in[12];
    const float* bq          = (const float*)d_in[13];
    const float* wk          = (const float*)d_in[14];
    const float* bk          = (const float*)d_in[15];
    const float* wv          = (const float*)d_in[16];
    const float* bv          = (const float*)d_in[17];
    const float* wo          = (const float*)d_in[18];
    const float* bo          = (const float*)d_in[19];
    const float* ln2_g       = (const float*)d_in[20];
    const float* ln2_b       = (const float*)d_in[21];
    const float* w1          = (const float*)d_in[22];
    const float* b1          = (const float*)d_in[23];
    const float* w2          = (const float*)d_in[24];
    const float* b2          = (const float*)d_in[25];
    const float* lnf_g       = (const float*)d_in[26];
    const float* lnf_b       = (const float*)d_in[27];
    float* out = (float*)d_out;

    float *h, *qkv, *bqkv;
    __half *hn, *ctx, *ff, *wt;
    cudaGetSymbolAddress((void**)&h,    g_h);
    cudaGetSymbolAddress((void**)&hn,   g_hn);
    cudaGetSymbolAddress((void**)&qkv,  g_qkv);
    cudaGetSymbolAddress((void**)&ctx,  g_ctx);
    cudaGetSymbolAddress((void**)&ff,   g_ff);
    cudaGetSymbolAddress((void**)&wt,   g_wt);
    cudaGetSymbolAddress((void**)&bqkv, g_bqkv);

    cudaFuncSetAttribute((const void*)mma_gemm<0,0,float>,  cudaFuncAttributeMaxDynamicSharedMemorySize, SMEM_GEMM);
    cudaFuncSetAttribute((const void*)mma_gemm<0,1,float>,  cudaFuncAttributeMaxDynamicSharedMemorySize, SMEM_GEMM);
    cudaFuncSetAttribute((const void*)mma_gemm<1,0,__half>, cudaFuncAttributeMaxDynamicSharedMemorySize, SMEM_GEMM);
    cudaFuncSetAttribute((const void*)flash_kernel,         cudaFuncAttributeMaxDynamicSharedMemorySize, SMEM_FLASH);

    // weight transposes (+ fp16 convert): rows 0..511 = wq, 512.. = wk, 1024.. = wv
    dim3 tb(32, 8);
    for (int l = 0; l < NLAYER; l++) {
        __half* base = wt + (size_t)l*WT_LSTRIDE;
        transpose_f16<<<dim3(16,16), tb>>>(wq + (size_t)l*DD*DD,  base,           DD, DD);
        transpose_f16<<<dim3(16,16), tb>>>(wk + (size_t)l*DD*DD,  base + 262144,  DD, DD);
        transpose_f16<<<dim3(16,16), tb>>>(wv + (size_t)l*DD*DD,  base + 524288,  DD, DD);
        transpose_f16<<<dim3(16,16), tb>>>(wo + (size_t)l*DD*DD,  base + 786432,  DD, DD);
        transpose_f16<<<dim3(16,64), tb>>>(w1 + (size_t)l*DD*FFD, base + 1048576, DD, FFD);
        transpose_f16<<<dim3(64,16), tb>>>(w2 + (size_t)l*FFD*DD, base + 2097152, FFD, DD);
    }
    concat_bias<<<dim3(6, NLAYER), 256>>>(bq, bk, bv, bqkv);

    embed_kernel<<<(TT*(DD/4))/256, 256>>>(x, emb, rate1, h);
    atom_kernel<<<NATOM, 128>>>(atoms_coord, atoms_token, atoms_index, batch_index,
                                emb, coord_w, coord_b, rate2, h);

    dim3 gD(DD/128, TT/128);       // (4, 512)
    dim3 gQKV(QKVD/128, TT/128);   // (12, 512)
    dim3 gF(FFD/128, TT/128);      // (16, 512)
    dim3 gFA(LL/64, BB*HH);        // (4, 2048)

    for (int l = 0; l < NLAYER; l++) {
        __half* base = wt + (size_t)l*WT_LSTRIDE;
        const __half* wtqkv = base;
        const __half* wto = base + 786432;
        const __half* wt1 = base + 1048576;
        const __half* wt2 = base + 2097152;

        ln_kernel<<<TT, 256>>>(h, hn, ln1_g + l*DD, ln1_b + l*DD);
        mma_gemm<0,0,float><<<gQKV, 256, SMEM_GEMM>>>(DD, hn, wtqkv, bqkv + (size_t)l*QKVD,
                                                      nullptr, qkv, QKVD);
        flash_kernel<<<gFA, 256, SMEM_FLASH>>>(qkv, x, ctx);
        mma_gemm<0,1,float><<<gD, 256, SMEM_GEMM>>>(DD, ctx, wto, bo + l*DD, h, h, DD);
        ln_kernel<<<TT, 256>>>(h, hn, ln2_g + l*DD, ln2_b + l*DD);
        mma_gemm<1,0,__half><<<gF, 256, SMEM_GEMM>>>(DD, hn, wt1, b1 + l*FFD, nullptr, ff, FFD);
        mma_gemm<0,1,float><<<gD, 256, SMEM_GEMM>>>(FFD, ff, wt2, b2 + l*DD, h, h, DD);
    }
    lnf_kernel<<<TT, 256>>>(h, out, lnf_g, lnf_b);
}

// round 7
// speedup vs baseline: 6.2390x; 1.4020x over previous
#include <cuda_runtime.h>
#include <cuda_fp16.h>
#include <math.h>
#include <stdint.h>

// Problem constants
#define BB 256
#define LL 256
#define DD 512
#define HH 8
#define DHH 64
#define NLAYER 6
#define FFD 2048
#define TT (BB*LL)          // 65536 tokens
#define NATOM 32768
#define QKVD 1536

// ---------------- scratch (device globals; no allocation allowed) -----------
__device__ float  g_h  [(size_t)TT*DD];
__device__ __half g_hn [(size_t)TT*DD];
__device__ __half g_qkv[(size_t)TT*QKVD];      // 201 MB
__device__ __half g_ctx[(size_t)TT*DD];
__device__ __half g_ff [(size_t)TT*FFD];       // 268 MB
#define WT_LSTRIDE 3145728
__device__ __half g_wt [(size_t)NLAYER*WT_LSTRIDE];  // 37.7 MB
__device__ float  g_bqkv[(size_t)NLAYER*QKVD];

// ---------------- small helpers ----------------------------------------------
__device__ __forceinline__ uint32_t smem_u32(const void* p) {
    uint32_t a;
    asm("{ .reg .u64 t; cvta.to.shared.u64 t, %1; cvt.u32.u64 %0, t; }" : "=r"(a) : "l"(p));
    return a;
}
__device__ __forceinline__ void cp_async16(uint32_t dst, const void* src) {
    asm volatile("cp.async.ca.shared.global [%0], [%1], 16;" :: "r"(dst), "l"(src) : "memory");
}
__device__ __forceinline__ void cp_commit() {
    asm volatile("cp.async.commit_group;" ::: "memory");
}
template<int N>
__device__ __forceinline__ void cp_wait() {
    asm volatile("cp.async.wait_group %0;" :: "n"(N) : "memory");
}
__device__ __forceinline__ void mma_f16(float& d0, float& d1, float& d2, float& d3,
                                        uint32_t a0, uint32_t a1, uint32_t a2, uint32_t a3,
                                        uint32_t b0, uint32_t b1) {
    asm volatile(
        "mma.sync.aligned.m16n8k16.row.col.f32.f16.f16.f32 "
        "{%0,%1,%2,%3}, {%4,%5,%6,%7}, {%8,%9}, {%0,%1,%2,%3};"
        : "+f"(d0), "+f"(d1), "+f"(d2), "+f"(d3)
        : "r"(a0), "r"(a1), "r"(a2), "r"(a3), "r"(b0), "r"(b1));
}
__device__ __forceinline__ uint32_t pack_h2(float a, float b) {
    __half2 h = __floats2half2_rn(a, b);
    return *(uint32_t*)&h;
}
// output store helpers
__device__ __forceinline__ void store_pair(float* p, float vx, float vy) {
    *(float2*)p = make_float2(vx, vy);
}
__device__ __forceinline__ void store_pair(__half* p, float vx, float vy) {
    *(__half2*)p = __floats2half2_rn(vx, vy);
}

// ---------------- block reduce ----------------------------------------------
template<bool DOMAX>
__device__ __forceinline__ float block_reduce(float v, float* red) {
    __syncthreads();
    #pragma unroll
    for (int o = 16; o; o >>= 1) {
        float other = __shfl_xor_sync(0xffffffffu, v, o);
        v = DOMAX ? fmaxf(v, other) : (v + other);
    }
    if ((threadIdx.x & 31) == 0) red[threadIdx.x >> 5] = v;
    __syncthreads();
    if (threadIdx.x == 0) {
        float t = red[0];
        #pragma unroll
        for (int i = 1; i < 8; i++) t = DOMAX ? fmaxf(t, red[i]) : (t + red[i]);
        red[0] = t;
    }
    __syncthreads();
    return red[0];
}

// ---------------- embedding -------------------------------------------------
__global__ void embed_kernel(const int* __restrict__ x, const float* __restrict__ emb,
                             const float* __restrict__ rate1, float* __restrict__ h) {
    int idx = blockIdx.x * blockDim.x + threadIdx.x;
    int t = idx / (DD/4);
    int c = idx % (DD/4);
    int b = t / LL, l = t % LL;
    int tok = x[l*BB + b];
    float4 e = ((const float4*)(emb + (size_t)tok*DD))[c];
    float r = rate1[0];
    ((float4*)(h + (size_t)t*DD))[c] = make_float4(r*e.x, r*e.y, r*e.z, r*e.w);
}

__global__ void atom_kernel(const float* __restrict__ coord, const int* __restrict__ atok,
                            const int* __restrict__ aidx, const int* __restrict__ bidx,
                            const float* __restrict__ emb, const float* __restrict__ cw,
                            const float* __restrict__ cb, const float* __restrict__ rate2,
                            float* __restrict__ h) {
    int a = blockIdx.x;
    int tok = atok[a];
    float c0 = coord[a*3+0], c1 = coord[a*3+1], c2 = coord[a*3+2];
    size_t row = (size_t)(bidx[a]*LL + aidx[a] + 1) * DD;
    float r = rate2[0];
    for (int i = threadIdx.x; i < DD; i += blockDim.x) {
        float val = emb[(size_t)tok*DD + i] + c0*cw[i] + c1*cw[DD+i] + c2*cw[2*DD+i] + cb[i];
        h[row + i] += r * val;
    }
}

// ---------------- layernorm (half output: feeds fp16 tensor GEMMs) ----------
__global__ void ln_kernel(const float* __restrict__ in, __half* __restrict__ out,
                          const float* __restrict__ g, const float* __restrict__ bt) {
    __shared__ float red[8];
    size_t t = blockIdx.x;
    const float* row = in + t*DD;
    int tid = threadIdx.x;
    float v0 = row[tid], v1 = row[tid+256];
    float mean = block_reduce<false>(v0+v1, red) * (1.0f/DD);
    float d0 = v0-mean, d1 = v1-mean;
    float var = block_reduce<false>(d0*d0+d1*d1, red) * (1.0f/DD);
    float rs = rsqrtf(var + 1e-6f);
    out[t*DD+tid]     = __float2half(d0*rs*g[tid]     + bt[tid]);
    out[t*DD+tid+256] = __float2half(d1*rs*g[tid+256] + bt[tid+256]);
}

// final LN + transpose [B,L,D] -> [L,B,D]
__global__ void lnf_kernel(const float* __restrict__ in, float* __restrict__ out,
                           const float* __restrict__ g, const float* __restrict__ bt) {
    __shared__ float red[8];
    size_t t = blockIdx.x;
    int b = (int)(t / LL), l = (int)(t % LL);
    const float* row = in + t*DD;
    int tid = threadIdx.x;
    float v0 = row[tid], v1 = row[tid+256];
    float mean = block_reduce<false>(v0+v1, red) * (1.0f/DD);
    float d0 = v0-mean, d1 = v1-mean;
    float var = block_reduce<false>(d0*d0+d1*d1, red) * (1.0f/DD);
    float rs = rsqrtf(var + 1e-6f);
    size_t o = (size_t)(l*BB + b) * DD;
    out[o+tid]     = d0*rs*g[tid]     + bt[tid];
    out[o+tid+256] = d1*rs*g[tid+256] + bt[tid+256];
}

// ---------------- weight transpose + fp16 convert: Wt[n,k] = h(W[k,n]) ------
__global__ void transpose_f16(const float* __restrict__ W, __half* __restrict__ Wt,
                              int K, int N) {
    __shared__ float t[32][33];
    int k0 = blockIdx.x*32, n0 = blockIdx.y*32;
    int tx = threadIdx.x, ty = threadIdx.y;
    for (int i = ty; i < 32; i += 8)
        t[i][tx] = W[(size_t)(k0+i)*N + n0 + tx];
    __syncthreads();
    for (int i = ty; i < 32; i += 8)
        Wt[(size_t)(n0+i)*K + k0 + tx] = __float2half(t[tx][i]);
}

// ---------------- concat QKV bias --------------------------------------------
__global__ void concat_bias(const float* __restrict__ bq, const float* __restrict__ bk,
                            const float* __restrict__ bv, float* __restrict__ bqkv) {
    int l = blockIdx.y;
    int i = blockIdx.x*256 + threadIdx.x;
    float v;
    if (i < 512)       v = bq[l*DD + i];
    else if (i < 1024) v = bk[l*DD + i - 512];
    else               v = bv[l*DD + i - 1024];
    bqkv[(size_t)l*QKVD + i] = v;
}

// ---------------- fp16 mma GEMM: C[M,N] = A[M,K] @ Wt[N,K]^T + bias ----------
#define SROWH 72
#define TILEH (128*SROWH)
#define SMEM_GEMM (4*TILEH*2)          // 73728 bytes

template<int RELU, int RESID, typename OutT>
__global__ void __launch_bounds__(256)
mma_gemm(int K, const __half* __restrict__ A, const __half* __restrict__ Bt,
         const float* __restrict__ bias, const float* __restrict__ Res,
         OutT* __restrict__ C, int N) {
    extern __shared__ __align__(16) __half hdyn[];
    __half* sA = hdyn;
    __half* sB = hdyn + 2*TILEH;
    uint32_t sA_u = smem_u32(sA);
    uint32_t sB_u = smem_u32(sB);

    int tid = threadIdx.x;
    int wid = tid >> 5, lane = tid & 31;
    int warp_m = wid >> 1;
    int warp_n = wid & 1;
    int bm = blockIdx.y, bn = blockIdx.x;

    const __half* Abase = A  + (size_t)bm*128*K;
    const __half* Bbase = Bt + (size_t)bn*128*K;

    auto load_tile = [&](int buf, int c) {
        const __half* Ap = Abase + c*64;
        const __half* Bp = Bbase + c*64;
        uint32_t sa = sA_u + (uint32_t)buf*TILEH*2;
        uint32_t sb = sB_u + (uint32_t)buf*TILEH*2;
        #pragma unroll
        for (int i = 0; i < 4; i++) {
            int cid = tid + i*256;
            int row = cid >> 3;
            int kc  = cid & 7;
            uint32_t soff = (uint32_t)(row*144 + kc*16);
            cp_async16(sa + soff, Ap + (size_t)row*K + kc*8);
            cp_async16(sb + soff, Bp + (size_t)row*K + kc*8);
        }
    };

    float acc[2][8][4];
    #pragma unroll
    for (int mt = 0; mt < 2; mt++)
        #pragma unroll
        for (int nt = 0; nt < 8; nt++)
            #pragma unroll
            for (int j = 0; j < 4; j++) acc[mt][nt][j] = 0.f;

    int NC = K >> 6;
    load_tile(0, 0);
    cp_commit();

    int r = lane >> 2;
    int cq = lane & 3;

    for (int c = 0; c < NC; c++) {
        int buf = c & 1;
        if (c + 1 < NC) {
            load_tile(buf ^ 1, c + 1);
            cp_commit();
            cp_wait<1>();
        } else {
            cp_wait<0>();
        }
        __syncthreads();

        const __half* tA = sA + buf*TILEH;
        const __half* tB = sB + buf*TILEH;
        #pragma unroll
        for (int kk = 0; kk < 4; kk++) {
            int k0 = kk*16;
            uint32_t af[2][4];
            #pragma unroll
            for (int mt = 0; mt < 2; mt++) {
                int base = (warp_m*32 + mt*16 + r)*SROWH + k0 + 2*cq;
                af[mt][0] = *(const uint32_t*)&tA[base];
                af[mt][1] = *(const uint32_t*)&tA[base + 8*SROWH];
                af[mt][2] = *(const uint32_t*)&tA[base + 8];
                af[mt][3] = *(const uint32_t*)&tA[base + 8*SROWH + 8];
            }
            #pragma unroll
            for (int nt = 0; nt < 8; nt++) {
                int nb = (warp_n*64 + nt*8 + r)*SROWH + k0 + 2*cq;
                uint32_t b0 = *(const uint32_t*)&tB[nb];
                uint32_t b1 = *(const uint32_t*)&tB[nb + 8];
                #pragma unroll
                for (int mt = 0; mt < 2; mt++)
                    mma_f16(acc[mt][nt][0], acc[mt][nt][1], acc[mt][nt][2], acc[mt][nt][3],
                            af[mt][0], af[mt][1], af[mt][2], af[mt][3], b0, b1);
            }
        }
        __syncthreads();
    }

    #pragma unroll
    for (int mt = 0; mt < 2; mt++) {
        size_t m0 = (size_t)bm*128 + warp_m*32 + mt*16 + r;
        #pragma unroll
        for (int nt = 0; nt < 8; nt++) {
            int n = bn*128 + warp_n*64 + nt*8 + 2*cq;
            float2 bs = *(const float2*)(bias + n);
            #pragma unroll
            for (int half_i = 0; half_i < 2; half_i++) {
                size_t m = m0 + half_i*8;
                float vx = acc[mt][nt][half_i*2 + 0] + bs.x;
                float vy = acc[mt][nt][half_i*2 + 1] + bs.y;
                if (RESID) {
                    float2 rr = *(const float2*)(Res + m*N + n);
                    vx += rr.x; vy += rr.y;
                }
                if (RELU) {
                    vx = fmaxf(vx, 0.f);
                    vy = fmaxf(vy, 0.f);
                }
                store_pair(C + m*N + n, vx, vy);
            }
        }
    }
}

// ---------------- fp16 mma flash attention -----------------------------------
// grid (L/128, B*H), 256 threads = 8 warps, each warp owns 16 Q rows.
// Q fragments register-resident (pre-scaled 0.125). K tile [j][d] smem,
// V tile transposed [d][j] smem. P stays in registers (acc->A-frag repack).
#define FVS 72   // smem row stride (halves): conflict-free fragment loads

__global__ void __launch_bounds__(256)
flash_kernel(const __half* __restrict__ qkv, const int* __restrict__ x,
             __half* __restrict__ ctx) {
    __shared__ __align__(16) __half Ks[64*FVS];
    __shared__ __align__(16) __half Vt[64*FVS];
    __shared__ int padf[64];

    int bh = blockIdx.y, b = bh >> 3, h = bh & 7;
    int i0 = blockIdx.x * 128;
    int tid = threadIdx.x;
    int wid = tid >> 5, lane = tid & 31;
    int r = lane >> 2, c2 = (lane & 3) * 2;

    // ---- Q fragments (row-block wid*16, scaled by 1/8 exactly) ----
    uint32_t qf[4][4];
    {
        const __half2 sc = __float2half2_rn(0.125f);
        size_t row0 = (size_t)(b*LL + i0 + wid*16 + r) * QKVD + h*DHH;
        #pragma unroll
        for (int k = 0; k < 4; k++) {
            __half2 v0 = *(const __half2*)(qkv + row0 + k*16 + c2);
            __half2 v1 = *(const __half2*)(qkv + row0 + 8*QKVD + k*16 + c2);
            __half2 v2 = *(const __half2*)(qkv + row0 + k*16 + 8 + c2);
            __half2 v3 = *(const __half2*)(qkv + row0 + 8*QKVD + k*16 + 8 + c2);
            v0 = __hmul2(v0, sc); v1 = __hmul2(v1, sc);
            v2 = __hmul2(v2, sc); v3 = __hmul2(v3, sc);
            qf[k][0] = *(uint32_t*)&v0; qf[k][1] = *(uint32_t*)&v1;
            qf[k][2] = *(uint32_t*)&v2; qf[k][3] = *(uint32_t*)&v3;
        }
    }

    float Oa[8][4];
    #pragma unroll
    for (int nt = 0; nt < 8; nt++)
        #pragma unroll
        for (int j = 0; j < 4; j++) Oa[nt][j] = 0.f;
    float m0 = -1e30f, m1 = -1e30f, s0 = 0.f, s1 = 0.f;

    uint32_t Ks_u = smem_u32(Ks);

    for (int kt = 0; kt < 4; kt++) {
        int j0 = kt * 64;
        __syncthreads();
        // K tile: 512 x 16B chunks via cp.async
        #pragma unroll
        for (int i = 0; i < 2; i++) {
            int cid = tid + i*256;
            int row = cid >> 3, kc = cid & 7;
            cp_async16(Ks_u + (uint32_t)(row*FVS + kc*8)*2,
                       qkv + (size_t)(b*LL + j0 + row)*QKVD + 512 + h*DHH + kc*8);
        }
        cp_commit();
        // V tile transposed: regular loads + scalar transposed stores
        #pragma unroll
        for (int i = 0; i < 2; i++) {
            int cid = tid + i*256;
            int row = cid >> 3, kc = cid & 7;
            union { uint4 u; __half hs[8]; } tmp;
            tmp.u = *(const uint4*)(qkv + (size_t)(b*LL + j0 + row)*QKVD + 1024 + h*DHH + kc*8);
            #pragma unroll
            for (int t = 0; t < 8; t++)
                Vt[(kc*8 + t)*FVS + row] = tmp.hs[t];
        }
        if (tid < 64) padf[tid] = (x[(j0 + tid)*BB + b] == 0);
        cp_wait<0>();
        __syncthreads();

        // ---- S = Qf @ K^T (already scaled) ----
        float S[8][4];
        #pragma unroll
        for (int nt = 0; nt < 8; nt++)
            #pragma unroll
            for (int j = 0; j < 4; j++) S[nt][j] = 0.f;
        #pragma unroll
        for (int k = 0; k < 4; k++) {
            #pragma unroll
            for (int nt = 0; nt < 8; nt++) {
                const __half* bp = &Ks[(nt*8 + r)*FVS + k*16 + c2];
                uint32_t b0 = *(const uint32_t*)bp;
                uint32_t b1 = *(const uint32_t*)(bp + 8);
                mma_f16(S[nt][0], S[nt][1], S[nt][2], S[nt][3],
                        qf[k][0], qf[k][1], qf[k][2], qf[k][3], b0, b1);
            }
        }
        // ---- mask ----
        #pragma unroll
        for (int nt = 0; nt < 8; nt++) {
            int j = nt*8 + c2;
            if (padf[j])     { S[nt][0] = -1e9f; S[nt][2] = -1e9f; }
            if (padf[j + 1]) { S[nt][1] = -1e9f; S[nt][3] = -1e9f; }
        }
        // ---- online softmax (rows r and r+8) ----
        float tm0 = -1e30f, tm1 = -1e30f;
        #pragma unroll
        for (int nt = 0; nt < 8; nt++) {
            tm0 = fmaxf(tm0, fmaxf(S[nt][0], S[nt][1]));
            tm1 = fmaxf(tm1, fmaxf(S[nt][2], S[nt][3]));
        }
        tm0 = fmaxf(tm0, __shfl_xor_sync(0xffffffffu, tm0, 1));
        tm0 = fmaxf(tm0, __shfl_xor_sync(0xffffffffu, tm0, 2));
        tm1 = fmaxf(tm1, __shfl_xor_sync(0xffffffffu, tm1, 1));
        tm1 = fmaxf(tm1, __shfl_xor_sync(0xffffffffu, tm1, 2));
        float mn0 = fmaxf(m0, tm0), mn1 = fmaxf(m1, tm1);
        float cr0 = __expf(m0 - mn0), cr1 = __expf(m1 - mn1);
        float rs0 = 0.f, rs1 = 0.f;
        #pragma unroll
        for (int nt = 0; nt < 8; nt++) {
            S[nt][0] = __expf(S[nt][0] - mn0); rs0 += S[nt][0];
            S[nt][1] = __expf(S[nt][1] - mn0); rs0 += S[nt][1];
            S[nt][2] = __expf(S[nt][2] - mn1); rs1 += S[nt][2];
            S[nt][3] = __expf(S[nt][3] - mn1); rs1 += S[nt][3];
        }
        rs0 += __shfl_xor_sync(0xffffffffu, rs0, 1);
        rs0 += __shfl_xor_sync(0xffffffffu, rs0, 2);
        rs1 += __shfl_xor_sync(0xffffffffu, rs1, 1);
        rs1 += __shfl_xor_sync(0xffffffffu, rs1, 2);
        s0 = s0*cr0 + rs0;  s1 = s1*cr1 + rs1;
        m0 = mn0;  m1 = mn1;
        #pragma unroll
        for (int nt = 0; nt < 8; nt++) {
            Oa[nt][0] *= cr0; Oa[nt][1] *= cr0;
            Oa[nt][2] *= cr1; Oa[nt][3] *= cr1;
        }
        // ---- P accumulator -> A-fragment repack (registers only) ----
        uint32_t pa[4][4];
        #pragma unroll
        for (int k = 0; k < 4; k++) {
            pa[k][0] = pack_h2(S[2*k][0],   S[2*k][1]);
            pa[k][1] = pack_h2(S[2*k][2],   S[2*k][3]);
            pa[k][2] = pack_h2(S[2*k+1][0], S[2*k+1][1]);
            pa[k][3] = pack_h2(S[2*k+1][2], S[2*k+1][3]);
        }
        // ---- O += P @ V ----
        #pragma unroll
        for (int k = 0; k < 4; k++) {
            #pragma unroll
            for (int nt = 0; nt < 8; nt++) {
                const __half* bp = &Vt[(nt*8 + r)*FVS + k*16 + c2];
                uint32_t b0 = *(const uint32_t*)bp;
                uint32_t b1 = *(const uint32_t*)(bp + 8);
                mma_f16(Oa[nt][0], Oa[nt][1], Oa[nt][2], Oa[nt][3],
                        pa[k][0], pa[k][1], pa[k][2], pa[k][3], b0, b1);
            }
        }
    }

    // ---- epilogue ----
    float inv0 = 1.0f / s0, inv1 = 1.0f / s1;
    size_t row0 = (size_t)(b*LL + i0 + wid*16 + r) * DD + h*DHH;
    size_t row8 = row0 + 8*DD;
    #pragma unroll
    for (int nt = 0; nt < 8; nt++) {
        *(__half2*)(ctx + row0 + nt*8 + c2) = __floats2half2_rn(Oa[nt][0]*inv0, Oa[nt][1]*inv0);
        *(__half2*)(ctx + row8 + nt*8 + c2) = __floats2half2_rn(Oa[nt][2]*inv1, Oa[nt][3]*inv1);
    }
}

// ---------------- host driver ------------------------------------------------
extern "C" void kernel_launch(void* const* d_in, const int* in_sizes, int n_in,
                              void* d_out, int out_size) {
    const int*   x           = (const int*)  d_in[0];
    const float* atoms_coord = (const float*)d_in[1];
    const int*   atoms_token = (const int*)  d_in[2];
    const int*   atoms_index = (const int*)  d_in[3];
    const int*   batch_index = (const int*)  d_in[4];
    const float* emb         = (const float*)d_in[5];
    const float* coord_w     = (const float*)d_in[6];
    const float* coord_b     = (const float*)d_in[7];
    const float* rate1       = (const float*)d_in[8];
    const float* rate2       = (const float*)d_in[9];
    const float* ln1_g       = (const float*)d_in[10];
    const float* ln1_b       = (const float*)d_in[11];
    const float* wq          = (const float*)d_in[12];
    const float* bq          = (const float*)d_in[13];
    const float* wk          = (const float*)d_in[14];
    const float* bk          = (const float*)d_in[15];
    const float* wv          = (const float*)d_in[16];
    const float* bv          = (const float*)d_in[17];
    const float* wo          = (const float*)d_in[18];
    const float* bo          = (const float*)d_in[19];
    const float* ln2_g       = (const float*)d_in[20];
    const float* ln2_b       = (const float*)d_in[21];
    const float* w1          = (const float*)d_in[22];
    const float* b1          = (const float*)d_in[23];
    const float* w2          = (const float*)d_in[24];
    const float* b2          = (const float*)d_in[25];
    const float* lnf_g       = (const float*)d_in[26];
    const float* lnf_b       = (const float*)d_in[27];
    float* out = (float*)d_out;

    float *h, *bqkv;
    __half *hn, *qkv, *ctx, *ff, *wt;
    cudaGetSymbolAddress((void**)&h,    g_h);
    cudaGetSymbolAddress((void**)&hn,   g_hn);
    cudaGetSymbolAddress((void**)&qkv,  g_qkv);
    cudaGetSymbolAddress((void**)&ctx,  g_ctx);
    cudaGetSymbolAddress((void**)&ff,   g_ff);
    cudaGetSymbolAddress((void**)&wt,   g_wt);
    cudaGetSymbolAddress((void**)&bqkv, g_bqkv);

    cudaFuncSetAttribute((const void*)mma_gemm<0,0,__half>, cudaFuncAttributeMaxDynamicSharedMemorySize, SMEM_GEMM);
    cudaFuncSetAttribute((const void*)mma_gemm<0,1,float>,  cudaFuncAttributeMaxDynamicSharedMemorySize, SMEM_GEMM);
    cudaFuncSetAttribute((const void*)mma_gemm<1,0,__half>, cudaFuncAttributeMaxDynamicSharedMemorySize, SMEM_GEMM);

    // weight transposes (+ fp16 convert): rows 0..511 = wq, 512.. = wk, 1024.. = wv
    dim3 tb(32, 8);
    for (int l = 0; l < NLAYER; l++) {
        __half* base = wt + (size_t)l*WT_LSTRIDE;
        transpose_f16<<<dim3(16,16), tb>>>(wq + (size_t)l*DD*DD,  base,           DD, DD);
        transpose_f16<<<dim3(16,16), tb>>>(wk + (size_t)l*DD*DD,  base + 262144,  DD, DD);
        transpose_f16<<<dim3(16,16), tb>>>(wv + (size_t)l*DD*DD,  base + 524288,  DD, DD);
        transpose_f16<<<dim3(16,16), tb>>>(wo + (size_t)l*DD*DD,  base + 786432,  DD, DD);
        transpose_f16<<<dim3(16,64), tb>>>(w1 + (size_t)l*DD*FFD, base + 1048576, DD, FFD);
        transpose_f16<<<dim3(64,16), tb>>>(w2 + (size_t)l*FFD*DD, base + 2097152, FFD, DD);
    }
    concat_bias<<<dim3(6, NLAYER), 256>>>(bq, bk, bv, bqkv);

    embed_kernel<<<(TT*(DD/4))/256, 256>>>(x, emb, rate1, h);
    atom_kernel<<<NATOM, 128>>>(atoms_coord, atoms_token, atoms_index, batch_index,
                                emb, coord_w, coord_b, rate2, h);

    dim3 gD(DD/128, TT/128);       // (4, 512)
    dim3 gQKV(QKVD/128, TT/128);   // (12, 512)
    dim3 gF(FFD/128, TT/128);      // (16, 512)
    dim3 gFA(LL/128, BB*HH);       // (2, 2048)

    for (int l = 0; l < NLAYER; l++) {
        __half* base = wt + (size_t)l*WT_LSTRIDE;
        const __half* wtqkv = base;
        const __half* wto = base + 786432;
        const __half* wt1 = base + 1048576;
        const __half* wt2 = base + 2097152;

        ln_kernel<<<TT, 256>>>(h, hn, ln1_g + l*DD, ln1_b + l*DD);
        mma_gemm<0,0,__half><<<gQKV, 256, SMEM_GEMM>>>(DD, hn, wtqkv, bqkv + (size_t)l*QKVD,
                                                       nullptr, qkv, QKVD);
        flash_kernel<<<gFA, 256>>>(qkv, x, ctx);
        mma_gemm<0,1,float><<<gD, 256, SMEM_GEMM>>>(DD, ctx, wto, bo + l*DD, h, h, DD);
        ln_kernel<<<TT, 256>>>(h, hn, ln2_g + l*DD, ln2_b + l*DD);
        mma_gemm<1,0,__half><<<gF, 256, SMEM_GEMM>>>(DD, hn, wt1, b1 + l*FFD, nullptr, ff, FFD);
        mma_gemm<0,1,float><<<gD, 256, SMEM_GEMM>>>(FFD, ff, wt2, b2 + l*DD, h, h, DD);
    }
    lnf_kernel<<<TT, 256>>>(h, out, lnf_g, lnf_b);
}

// round 8
// speedup vs baseline: 6.6116x; 1.0597x over previous
#include <cuda_runtime.h>
#include <cuda_fp16.h>
#include <math.h>
#include <stdint.h>

// Problem constants
#define BB 256
#define LL 256
#define DD 512
#define HH 8
#define DHH 64
#define NLAYER 6
#define FFD 2048
#define TT (BB*LL)          // 65536 tokens
#define NATOM 32768
#define QKVD 1536

// ---------------- scratch (device globals; no allocation allowed) -----------
__device__ float  g_h  [(size_t)TT*DD];
__device__ __half g_hn [(size_t)TT*DD];
__device__ __half g_qkv[(size_t)TT*QKVD];      // 201 MB
__device__ __half g_ctx[(size_t)TT*DD];
__device__ __half g_ff [(size_t)TT*FFD];       // 268 MB
#define WT_LSTRIDE 3145728
__device__ __half g_wt [(size_t)NLAYER*WT_LSTRIDE];  // 37.7 MB
__device__ float  g_bqkv[(size_t)NLAYER*QKVD];

// ---------------- small helpers ----------------------------------------------
__device__ __forceinline__ uint32_t smem_u32(const void* p) {
    uint32_t a;
    asm("{ .reg .u64 t; cvta.to.shared.u64 t, %1; cvt.u32.u64 %0, t; }" : "=r"(a) : "l"(p));
    return a;
}
__device__ __forceinline__ void cp_async16(uint32_t dst, const void* src) {
    asm volatile("cp.async.cg.shared.global [%0], [%1], 16;" :: "r"(dst), "l"(src) : "memory");
}
__device__ __forceinline__ void cp_commit() {
    asm volatile("cp.async.commit_group;" ::: "memory");
}
template<int N>
__device__ __forceinline__ void cp_wait() {
    asm volatile("cp.async.wait_group %0;" :: "n"(N) : "memory");
}
__device__ __forceinline__ void mma_f16(float& d0, float& d1, float& d2, float& d3,
                                        uint32_t a0, uint32_t a1, uint32_t a2, uint32_t a3,
                                        uint32_t b0, uint32_t b1) {
    asm volatile(
        "mma.sync.aligned.m16n8k16.row.col.f32.f16.f16.f32 "
        "{%0,%1,%2,%3}, {%4,%5,%6,%7}, {%8,%9}, {%0,%1,%2,%3};"
        : "+f"(d0), "+f"(d1), "+f"(d2), "+f"(d3)
        : "r"(a0), "r"(a1), "r"(a2), "r"(a3), "r"(b0), "r"(b1));
}
__device__ __forceinline__ void ldmatrix_x4(uint32_t& r0, uint32_t& r1, uint32_t& r2, uint32_t& r3,
                                            uint32_t addr) {
    asm volatile("ldmatrix.sync.aligned.m8n8.x4.shared.b16 {%0,%1,%2,%3}, [%4];"
                 : "=r"(r0), "=r"(r1), "=r"(r2), "=r"(r3) : "r"(addr));
}
__device__ __forceinline__ uint32_t pack_h2(float a, float b) {
    __half2 h = __floats2half2_rn(a, b);
    return *(uint32_t*)&h;
}
// output store helpers
__device__ __forceinline__ void store_pair(float* p, float vx, float vy) {
    *(float2*)p = make_float2(vx, vy);
}
__device__ __forceinline__ void store_pair(__half* p, float vx, float vy) {
    *(__half2*)p = __floats2half2_rn(vx, vy);
}

// ---------------- block reduce ----------------------------------------------
template<bool DOMAX>
__device__ __forceinline__ float block_reduce(float v, float* red) {
    __syncthreads();
    #pragma unroll
    for (int o = 16; o; o >>= 1) {
        float other = __shfl_xor_sync(0xffffffffu, v, o);
        v = DOMAX ? fmaxf(v, other) : (v + other);
    }
    if ((threadIdx.x & 31) == 0) red[threadIdx.x >> 5] = v;
    __syncthreads();
    if (threadIdx.x == 0) {
        float t = red[0];
        #pragma unroll
        for (int i = 1; i < 8; i++) t = DOMAX ? fmaxf(t, red[i]) : (t + red[i]);
        red[0] = t;
    }
    __syncthreads();
    return red[0];
}

// ---------------- embedding -------------------------------------------------
__global__ void embed_kernel(const int* __restrict__ x, const float* __restrict__ emb,
                             const float* __restrict__ rate1, float* __restrict__ h) {
    int idx = blockIdx.x * blockDim.x + threadIdx.x;
    int t = idx / (DD/4);
    int c = idx % (DD/4);
    int b = t / LL, l = t % LL;
    int tok = x[l*BB + b];
    float4 e = ((const float4*)(emb + (size_t)tok*DD))[c];
    float r = rate1[0];
    ((float4*)(h + (size_t)t*DD))[c] = make_float4(r*e.x, r*e.y, r*e.z, r*e.w);
}

__global__ void atom_kernel(const float* __restrict__ coord, const int* __restrict__ atok,
                            const int* __restrict__ aidx, const int* __restrict__ bidx,
                            const float* __restrict__ emb, const float* __restrict__ cw,
                            const float* __restrict__ cb, const float* __restrict__ rate2,
                            float* __restrict__ h) {
    int a = blockIdx.x;
    int tok = atok[a];
    float c0 = coord[a*3+0], c1 = coord[a*3+1], c2 = coord[a*3+2];
    size_t row = (size_t)(bidx[a]*LL + aidx[a] + 1) * DD;
    float r = rate2[0];
    for (int i = threadIdx.x; i < DD; i += blockDim.x) {
        float val = emb[(size_t)tok*DD + i] + c0*cw[i] + c1*cw[DD+i] + c2*cw[2*DD+i] + cb[i];
        h[row + i] += r * val;
    }
}

// ---------------- layernorm (half output: feeds fp16 tensor GEMMs) ----------
__global__ void ln_kernel(const float* __restrict__ in, __half* __restrict__ out,
                          const float* __restrict__ g, const float* __restrict__ bt) {
    __shared__ float red[8];
    size_t t = blockIdx.x;
    const float* row = in + t*DD;
    int tid = threadIdx.x;
    float v0 = row[tid], v1 = row[tid+256];
    float mean = block_reduce<false>(v0+v1, red) * (1.0f/DD);
    float d0 = v0-mean, d1 = v1-mean;
    float var = block_reduce<false>(d0*d0+d1*d1, red) * (1.0f/DD);
    float rs = rsqrtf(var + 1e-6f);
    out[t*DD+tid]     = __float2half(d0*rs*g[tid]     + bt[tid]);
    out[t*DD+tid+256] = __float2half(d1*rs*g[tid+256] + bt[tid+256]);
}

// final LN + transpose [B,L,D] -> [L,B,D]
__global__ void lnf_kernel(const float* __restrict__ in, float* __restrict__ out,
                           const float* __restrict__ g, const float* __restrict__ bt) {
    __shared__ float red[8];
    size_t t = blockIdx.x;
    int b = (int)(t / LL), l = (int)(t % LL);
    const float* row = in + t*DD;
    int tid = threadIdx.x;
    float v0 = row[tid], v1 = row[tid+256];
    float mean = block_reduce<false>(v0+v1, red) * (1.0f/DD);
    float d0 = v0-mean, d1 = v1-mean;
    float var = block_reduce<false>(d0*d0+d1*d1, red) * (1.0f/DD);
    float rs = rsqrtf(var + 1e-6f);
    size_t o = (size_t)(l*BB + b) * DD;
    out[o+tid]     = d0*rs*g[tid]     + bt[tid];
    out[o+tid+256] = d1*rs*g[tid+256] + bt[tid+256];
}

// ---------------- weight transpose + fp16 convert: Wt[n,k] = h(W[k,n]) ------
__global__ void transpose_f16(const float* __restrict__ W, __half* __restrict__ Wt,
                              int K, int N) {
    __shared__ float t[32][33];
    int k0 = blockIdx.x*32, n0 = blockIdx.y*32;
    int tx = threadIdx.x, ty = threadIdx.y;
    for (int i = ty; i < 32; i += 8)
        t[i][tx] = W[(size_t)(k0+i)*N + n0 + tx];
    __syncthreads();
    for (int i = ty; i < 32; i += 8)
        Wt[(size_t)(n0+i)*K + k0 + tx] = __float2half(t[tx][i]);
}

// ---------------- concat QKV bias --------------------------------------------
__global__ void concat_bias(const float* __restrict__ bq, const float* __restrict__ bk,
                            const float* __restrict__ bv, float* __restrict__ bqkv) {
    int l = blockIdx.y;
    int i = blockIdx.x*256 + threadIdx.x;
    float v;
    if (i < 512)       v = bq[l*DD + i];
    else if (i < 1024) v = bk[l*DD + i - 512];
    else               v = bv[l*DD + i - 1024];
    bqkv[(size_t)l*QKVD + i] = v;
}

// ---------------- fp16 mma GEMM: C[M,N] = A[M,K] @ Wt[N,K]^T + bias ----------
// BM=BN=128, BK=64 halves, 256 threads = 8 warps (4 M x 2 N), warp tile 32x64.
// Fragment loads via ldmatrix.x4 (conflict-free at 144B row stride).
#define SROWH 72
#define TILEH (128*SROWH)
#define SMEM_GEMM (4*TILEH*2)          // 73728 bytes

template<int RELU, int RESID, typename OutT>
__global__ void __launch_bounds__(256)
mma_gemm(int K, const __half* __restrict__ A, const __half* __restrict__ Bt,
         const float* __restrict__ bias, const float* __restrict__ Res,
         OutT* __restrict__ C, int N) {
    extern __shared__ __align__(16) __half hdyn[];
    __half* sA = hdyn;
    __half* sB = hdyn + 2*TILEH;
    uint32_t sA_u = smem_u32(sA);
    uint32_t sB_u = smem_u32(sB);

    int tid = threadIdx.x;
    int wid = tid >> 5, lane = tid & 31;
    int warp_m = wid >> 1;
    int warp_n = wid & 1;
    int bm = blockIdx.y, bn = blockIdx.x;

    const __half* Abase = A  + (size_t)bm*128*K;
    const __half* Bbase = Bt + (size_t)bn*128*K;

    auto load_tile = [&](int buf, int c) {
        const __half* Ap = Abase + c*64;
        const __half* Bp = Bbase + c*64;
        uint32_t sa = sA_u + (uint32_t)buf*TILEH*2;
        uint32_t sb = sB_u + (uint32_t)buf*TILEH*2;
        #pragma unroll
        for (int i = 0; i < 4; i++) {
            int cid = tid + i*256;
            int row = cid >> 3;
            int kc  = cid & 7;
            uint32_t soff = (uint32_t)(row*144 + kc*16);
            cp_async16(sa + soff, Ap + (size_t)row*K + kc*8);
            cp_async16(sb + soff, Bp + (size_t)row*K + kc*8);
        }
    };

    float acc[2][8][4];
    #pragma unroll
    for (int mt = 0; mt < 2; mt++)
        #pragma unroll
        for (int nt = 0; nt < 8; nt++)
            #pragma unroll
            for (int j = 0; j < 4; j++) acc[mt][nt][j] = 0.f;

    int NC = K >> 6;
    load_tile(0, 0);
    cp_commit();

    int r = lane >> 2;      // 0..7
    int cq = lane & 3;      // 0..3
    // ldmatrix per-lane address offsets (bytes)
    int mi = lane >> 3, lr = lane & 7;
    uint32_t aoff[2], boff[4];
    #pragma unroll
    for (int mt = 0; mt < 2; mt++)
        aoff[mt] = (uint32_t)(((warp_m*32 + mt*16 + (mi & 1)*8 + lr)*SROWH + (mi >> 1)*8) * 2);
    #pragma unroll
    for (int ntp = 0; ntp < 4; ntp++)
        boff[ntp] = (uint32_t)(((warp_n*64 + ntp*16 + (mi >> 1)*8 + lr)*SROWH + (mi & 1)*8) * 2);

    for (int c = 0; c < NC; c++) {
        int buf = c & 1;
        if (c + 1 < NC) {
            load_tile(buf ^ 1, c + 1);
            cp_commit();
            cp_wait<1>();
        } else {
            cp_wait<0>();
        }
        __syncthreads();

        uint32_t tA_u = sA_u + (uint32_t)buf*TILEH*2;
        uint32_t tB_u = sB_u + (uint32_t)buf*TILEH*2;
        #pragma unroll
        for (int kk = 0; kk < 4; kk++) {
            uint32_t kof = (uint32_t)(kk*16*2);
            uint32_t af[2][4];
            ldmatrix_x4(af[0][0], af[0][1], af[0][2], af[0][3], tA_u + aoff[0] + kof);
            ldmatrix_x4(af[1][0], af[1][1], af[1][2], af[1][3], tA_u + aoff[1] + kof);
            #pragma unroll
            for (int ntp = 0; ntp < 4; ntp++) {
                uint32_t b0, b1, b2, b3;
                ldmatrix_x4(b0, b1, b2, b3, tB_u + boff[ntp] + kof);
                #pragma unroll
                for (int mt = 0; mt < 2; mt++) {
                    mma_f16(acc[mt][2*ntp][0],   acc[mt][2*ntp][1],   acc[mt][2*ntp][2],   acc[mt][2*ntp][3],
                            af[mt][0], af[mt][1], af[mt][2], af[mt][3], b0, b1);
                    mma_f16(acc[mt][2*ntp+1][0], acc[mt][2*ntp+1][1], acc[mt][2*ntp+1][2], acc[mt][2*ntp+1][3],
                            af[mt][0], af[mt][1], af[mt][2], af[mt][3], b2, b3);
                }
            }
        }
        __syncthreads();
    }

    #pragma unroll
    for (int mt = 0; mt < 2; mt++) {
        size_t m0 = (size_t)bm*128 + warp_m*32 + mt*16 + r;
        #pragma unroll
        for (int nt = 0; nt < 8; nt++) {
            int n = bn*128 + warp_n*64 + nt*8 + 2*cq;
            float2 bs = *(const float2*)(bias + n);
            #pragma unroll
            for (int half_i = 0; half_i < 2; half_i++) {
                size_t m = m0 + half_i*8;
                float vx = acc[mt][nt][half_i*2 + 0] + bs.x;
                float vy = acc[mt][nt][half_i*2 + 1] + bs.y;
                if (RESID) {
                    float2 rr = *(const float2*)(Res + m*N + n);
                    vx += rr.x; vy += rr.y;
                }
                if (RELU) {
                    vx = fmaxf(vx, 0.f);
                    vy = fmaxf(vy, 0.f);
                }
                store_pair(C + m*N + n, vx, vy);
            }
        }
    }
}

// ---------------- fp16 mma flash attention -----------------------------------
#define FVS 72

__global__ void __launch_bounds__(256)
flash_kernel(const __half* __restrict__ qkv, const int* __restrict__ x,
             __half* __restrict__ ctx) {
    __shared__ __align__(16) __half Ks[64*FVS];
    __shared__ __align__(16) __half Vt[64*FVS];
    __shared__ int padf[64];

    int bh = blockIdx.y, b = bh >> 3, h = bh & 7;
    int i0 = blockIdx.x * 128;
    int tid = threadIdx.x;
    int wid = tid >> 5, lane = tid & 31;
    int r = lane >> 2, c2 = (lane & 3) * 2;

    uint32_t qf[4][4];
    {
        const __half2 sc = __float2half2_rn(0.125f);
        size_t row0 = (size_t)(b*LL + i0 + wid*16 + r) * QKVD + h*DHH;
        #pragma unroll
        for (int k = 0; k < 4; k++) {
            __half2 v0 = *(const __half2*)(qkv + row0 + k*16 + c2);
            __half2 v1 = *(const __half2*)(qkv + row0 + 8*QKVD + k*16 + c2);
            __half2 v2 = *(const __half2*)(qkv + row0 + k*16 + 8 + c2);
            __half2 v3 = *(const __half2*)(qkv + row0 + 8*QKVD + k*16 + 8 + c2);
            v0 = __hmul2(v0, sc); v1 = __hmul2(v1, sc);
            v2 = __hmul2(v2, sc); v3 = __hmul2(v3, sc);
            qf[k][0] = *(uint32_t*)&v0; qf[k][1] = *(uint32_t*)&v1;
            qf[k][2] = *(uint32_t*)&v2; qf[k][3] = *(uint32_t*)&v3;
        }
    }

    float Oa[8][4];
    #pragma unroll
    for (int nt = 0; nt < 8; nt++)
        #pragma unroll
        for (int j = 0; j < 4; j++) Oa[nt][j] = 0.f;
    float m0 = -1e30f, m1 = -1e30f, s0 = 0.f, s1 = 0.f;

    uint32_t Ks_u = smem_u32(Ks);

    for (int kt = 0; kt < 4; kt++) {
        int j0 = kt * 64;
        __syncthreads();
        #pragma unroll
        for (int i = 0; i < 2; i++) {
            int cid = tid + i*256;
            int row = cid >> 3, kc = cid & 7;
            cp_async16(Ks_u + (uint32_t)(row*FVS + kc*8)*2,
                       qkv + (size_t)(b*LL + j0 + row)*QKVD + 512 + h*DHH + kc*8);
        }
        cp_commit();
        #pragma unroll
        for (int i = 0; i < 2; i++) {
            int cid = tid + i*256;
            int row = cid >> 3, kc = cid & 7;
            union { uint4 u; __half hs[8]; } tmp;
            tmp.u = *(const uint4*)(qkv + (size_t)(b*LL + j0 + row)*QKVD + 1024 + h*DHH + kc*8);
            #pragma unroll
            for (int t = 0; t < 8; t++)
                Vt[(kc*8 + t)*FVS + row] = tmp.hs[t];
        }
        if (tid < 64) padf[tid] = (x[(j0 + tid)*BB + b] == 0);
        cp_wait<0>();
        __syncthreads();

        float S[8][4];
        #pragma unroll
        for (int nt = 0; nt < 8; nt++)
            #pragma unroll
            for (int j = 0; j < 4; j++) S[nt][j] = 0.f;
        #pragma unroll
        for (int k = 0; k < 4; k++) {
            #pragma unroll
            for (int nt = 0; nt < 8; nt++) {
                const __half* bp = &Ks[(nt*8 + r)*FVS + k*16 + c2];
                uint32_t b0 = *(const uint32_t*)bp;
                uint32_t b1 = *(const uint32_t*)(bp + 8);
                mma_f16(S[nt][0], S[nt][1], S[nt][2], S[nt][3],
                        qf[k][0], qf[k][1], qf[k][2], qf[k][3], b0, b1);
            }
        }
        #pragma unroll
        for (int nt = 0; nt < 8; nt++) {
            int j = nt*8 + c2;
            if (padf[j])     { S[nt][0] = -1e9f; S[nt][2] = -1e9f; }
            if (padf[j + 1]) { S[nt][1] = -1e9f; S[nt][3] = -1e9f; }
        }
        float tm0 = -1e30f, tm1 = -1e30f;
        #pragma unroll
        for (int nt = 0; nt < 8; nt++) {
            tm0 = fmaxf(tm0, fmaxf(S[nt][0], S[nt][1]));
            tm1 = fmaxf(tm1, fmaxf(S[nt][2], S[nt][3]));
        }
        tm0 = fmaxf(tm0, __shfl_xor_sync(0xffffffffu, tm0, 1));
        tm0 = fmaxf(tm0, __shfl_xor_sync(0xffffffffu, tm0, 2));
        tm1 = fmaxf(tm1, __shfl_xor_sync(0xffffffffu, tm1, 1));
        tm1 = fmaxf(tm1, __shfl_xor_sync(0xffffffffu, tm1, 2));
        float mn0 = fmaxf(m0, tm0), mn1 = fmaxf(m1, tm1);
        float cr0 = __expf(m0 - mn0), cr1 = __expf(m1 - mn1);
        float rs0 = 0.f, rs1 = 0.f;
        #pragma unroll
        for (int nt = 0; nt < 8; nt++) {
            S[nt][0] = __expf(S[nt][0] - mn0); rs0 += S[nt][0];
            S[nt][1] = __expf(S[nt][1] - mn0); rs0 += S[nt][1];
            S[nt][2] = __expf(S[nt][2] - mn1); rs1 += S[nt][2];
            S[nt][3] = __expf(S[nt][3] - mn1); rs1 += S[nt][3];
        }
        rs0 += __shfl_xor_sync(0xffffffffu, rs0, 1);
        rs0 += __shfl_xor_sync(0xffffffffu, rs0, 2);
        rs1 += __shfl_xor_sync(0xffffffffu, rs1, 1);
        rs1 += __shfl_xor_sync(0xffffffffu, rs1, 2);
        s0 = s0*cr0 + rs0;  s1 = s1*cr1 + rs1;
        m0 = mn0;  m1 = mn1;
        #pragma unroll
        for (int nt = 0; nt < 8; nt++) {
            Oa[nt][0] *= cr0; Oa[nt][1] *= cr0;
            Oa[nt][2] *= cr1; Oa[nt][3] *= cr1;
        }
        uint32_t pa[4][4];
        #pragma unroll
        for (int k = 0; k < 4; k++) {
            pa[k][0] = pack_h2(S[2*k][0],   S[2*k][1]);
            pa[k][1] = pack_h2(S[2*k][2],   S[2*k][3]);
            pa[k][2] = pack_h2(S[2*k+1][0], S[2*k+1][1]);
            pa[k][3] = pack_h2(S[2*k+1][2], S[2*k+1][3]);
        }
        #pragma unroll
        for (int k = 0; k < 4; k++) {
            #pragma unroll
            for (int nt = 0; nt < 8; nt++) {
                const __half* bp = &Vt[(nt*8 + r)*FVS + k*16 + c2];
                uint32_t b0 = *(const uint32_t*)bp;
                uint32_t b1 = *(const uint32_t*)(bp + 8);
                mma_f16(Oa[nt][0], Oa[nt][1], Oa[nt][2], Oa[nt][3],
                        pa[k][0], pa[k][1], pa[k][2], pa[k][3], b0, b1);
            }
        }
    }

    float inv0 = 1.0f / s0, inv1 = 1.0f / s1;
    size_t row0 = (size_t)(b*LL + i0 + wid*16 + r) * DD + h*DHH;
    size_t row8 = row0 + 8*DD;
    #pragma unroll
    for (int nt = 0; nt < 8; nt++) {
        *(__half2*)(ctx + row0 + nt*8 + c2) = __floats2half2_rn(Oa[nt][0]*inv0, Oa[nt][1]*inv0);
        *(__half2*)(ctx + row8 + nt*8 + c2) = __floats2half2_rn(Oa[nt][2]*inv1, Oa[nt][3]*inv1);
    }
}

// ---------------- host driver ------------------------------------------------
extern "C" void kernel_launch(void* const* d_in, const int* in_sizes, int n_in,
                              void* d_out, int out_size) {
    const int*   x           = (const int*)  d_in[0];
    const float* atoms_coord = (const float*)d_in[1];
    const int*   atoms_token = (const int*)  d_in[2];
    const int*   atoms_index = (const int*)  d_in[3];
    const int*   batch_index = (const int*)  d_in[4];
    const float* emb         = (const float*)d_in[5];
    const float* coord_w     = (const float*)d_in[6];
    const float* coord_b     = (const float*)d_in[7];
    const float* rate1       = (const float*)d_in[8];
    const float* rate2       = (const float*)d_in[9];
    const float* ln1_g       = (const float*)d_in[10];
    const float* ln1_b       = (const float*)d_in[11];
    const float* wq          = (const float*)d_in[12];
    const float* bq          = (const float*)d_in[13];
    const float* wk          = (const float*)d_in[14];
    const float* bk          = (const float*)d_in[15];
    const float* wv          = (const float*)d_in[16];
    const float* bv          = (const float*)d_in[17];
    const float* wo          = (const float*)d_in[18];
    const float* bo          = (const float*)d_in[19];
    const float* ln2_g       = (const float*)d_in[20];
    const float* ln2_b       = (const float*)d_in[21];
    const float* w1          = (const float*)d_in[22];
    const float* b1          = (const float*)d_in[23];
    const float* w2          = (const float*)d_in[24];
    const float* b2          = (const float*)d_in[25];
    const float* lnf_g       = (const float*)d_in[26];
    const float* lnf_b       = (const float*)d_in[27];
    float* out = (float*)d_out;

    float *h, *bqkv;
    __half *hn, *qkv, *ctx, *ff, *wt;
    cudaGetSymbolAddress((void**)&h,    g_h);
    cudaGetSymbolAddress((void**)&hn,   g_hn);
    cudaGetSymbolAddress((void**)&qkv,  g_qkv);
    cudaGetSymbolAddress((void**)&ctx,  g_ctx);
    cudaGetSymbolAddress((void**)&ff,   g_ff);
    cudaGetSymbolAddress((void**)&wt,   g_wt);
    cudaGetSymbolAddress((void**)&bqkv, g_bqkv);

    cudaFuncSetAttribute((const void*)mma_gemm<0,0,__half>, cudaFuncAttributeMaxDynamicSharedMemorySize, SMEM_GEMM);
    cudaFuncSetAttribute((const void*)mma_gemm<0,1,float>,  cudaFuncAttributeMaxDynamicSharedMemorySize, SMEM_GEMM);
    cudaFuncSetAttribute((const void*)mma_gemm<1,0,__half>, cudaFuncAttributeMaxDynamicSharedMemorySize, SMEM_GEMM);

    // weight transposes (+ fp16 convert): rows 0..511 = wq, 512.. = wk, 1024.. = wv
    dim3 tb(32, 8);
    for (int l = 0; l < NLAYER; l++) {
        __half* base = wt + (size_t)l*WT_LSTRIDE;
        transpose_f16<<<dim3(16,16), tb>>>(wq + (size_t)l*DD*DD,  base,           DD, DD);
        transpose_f16<<<dim3(16,16), tb>>>(wk + (size_t)l*DD*DD,  base + 262144,  DD, DD);
        transpose_f16<<<dim3(16,16), tb>>>(wv + (size_t)l*DD*DD,  base + 524288,  DD, DD);
        transpose_f16<<<dim3(16,16), tb>>>(wo + (size_t)l*DD*DD,  base + 786432,  DD, DD);
        transpose_f16<<<dim3(16,64), tb>>>(w1 + (size_t)l*DD*FFD, base + 1048576, DD, FFD);
        transpose_f16<<<dim3(64,16), tb>>>(w2 + (size_t)l*FFD*DD, base + 2097152, FFD, DD);
    }
    concat_bias<<<dim3(6, NLAYER), 256>>>(bq, bk, bv, bqkv);

    embed_kernel<<<(TT*(DD/4))/256, 256>>>(x, emb, rate1, h);
    atom_kernel<<<NATOM, 128>>>(atoms_coord, atoms_token, atoms_index, batch_index,
                                emb, coord_w, coord_b, rate2, h);

    dim3 gD(DD/128, TT/128);       // (4, 512)
    dim3 gQKV(QKVD/128, TT/128);   // (12, 512)
    dim3 gF(FFD/128, TT/128);      // (16, 512)
    dim3 gFA(LL/128, BB*HH);       // (2, 2048)

    for (int l = 0; l < NLAYER; l++) {
        __half* base = wt + (size_t)l*WT_LSTRIDE;
        const __half* wtqkv = base;
        const __half* wto = base + 786432;
        const __half* wt1 = base + 1048576;
        const __half* wt2 = base + 2097152;

        ln_kernel<<<TT, 256>>>(h, hn, ln1_g + l*DD, ln1_b + l*DD);
        mma_gemm<0,0,__half><<<gQKV, 256, SMEM_GEMM>>>(DD, hn, wtqkv, bqkv + (size_t)l*QKVD,
                                                       nullptr, qkv, QKVD);
        flash_kernel<<<gFA, 256>>>(qkv, x, ctx);
        mma_gemm<0,1,float><<<gD, 256, SMEM_GEMM>>>(DD, ctx, wto, bo + l*DD, h, h, DD);
        ln_kernel<<<TT, 256>>>(h, hn, ln2_g + l*DD, ln2_b + l*DD);
        mma_gemm<1,0,__half><<<gF, 256, SMEM_GEMM>>>(DD, hn, wt1, b1 + l*FFD, nullptr, ff, FFD);
        mma_gemm<0,1,float><<<gD, 256, SMEM_GEMM>>>(FFD, ff, wt2, b2 + l*DD, h, h, DD);
    }
    lnf_kernel<<<TT, 256>>>(h, out, lnf_g, lnf_b);
}